// round 1
// baseline (speedup 1.0000x reference)
#include <cuda_runtime.h>
#include <cstdint>
#include <cstddef>

// ---------------- problem constants ----------------
#define B_  8
#define S_  1024
#define D_  1024
#define H_  8
#define HD_ 64
#define HID_ 512
#define P_  2048
#define KSZ 4
#define TOK (B_ * S_)          // 8192 tokens
#define EPS 1e-6f
#define CAP 15.0f

// ---------------- scratch (static device memory; no allocs allowed) ----------------
// offsets in floats
#define OFF_XN    ((size_t)0)                          // 8192*1024
#define OFF_XT    (OFF_XN  + (size_t)TOK * D_)         // 8192*2048
#define OFF_RT    (OFF_XT  + (size_t)TOK * P_)         // 8192*512
#define OFF_XC    (OFF_RT  + (size_t)TOK * HID_)       // 8192*2048
#define OFF_SKIP  (OFF_XC  + (size_t)TOK * P_)
#define OFF_Q     (OFF_SKIP+ (size_t)TOK * HID_)
#define OFF_K     (OFF_Q   + (size_t)TOK * HID_)
#define OFF_V     (OFF_K   + (size_t)TOK * HID_)
#define OFF_O     (OFF_V   + (size_t)TOK * HID_)
#define OFF_I     (OFF_O   + (size_t)TOK * HID_)       // 8192*8
#define OFF_F     (OFF_I   + (size_t)TOK * H_)
#define OFF_HS    (OFF_F   + (size_t)TOK * H_)         // 8192*512
#define OFF_U     (OFF_HS  + (size_t)TOK * HID_)
#define SCRATCH_TOTAL (OFF_U + (size_t)TOK * HID_)

__device__ float g_scratch[SCRATCH_TOTAL];

// ---------------- LayerNorm over D=1024, one block per token ----------------
__global__ void ln_kernel(const float* __restrict__ x, const float* __restrict__ g,
                          const float* __restrict__ b, float* __restrict__ out)
{
    int tok = blockIdx.x;
    int tid = threadIdx.x;                 // 256 threads
    const float4* xr = (const float4*)(x + (size_t)tok * D_);
    float4 v = xr[tid];
    float s1 = v.x + v.y + v.z + v.w;
    float s2 = v.x * v.x + v.y * v.y + v.z * v.z + v.w * v.w;

    // block reduce (8 warps)
    for (int o = 16; o > 0; o >>= 1) {
        s1 += __shfl_down_sync(0xffffffffu, s1, o);
        s2 += __shfl_down_sync(0xffffffffu, s2, o);
    }
    __shared__ float ps1[8], ps2[8];
    int wid = tid >> 5, lane = tid & 31;
    if (lane == 0) { ps1[wid] = s1; ps2[wid] = s2; }
    __syncthreads();
    float S1 = 0.f, S2 = 0.f;
    #pragma unroll
    for (int w = 0; w < 8; w++) { S1 += ps1[w]; S2 += ps2[w]; }
    float mu = S1 * (1.0f / D_);
    float var = S2 * (1.0f / D_) - mu * mu;
    float r = rsqrtf(var + EPS);

    float4 gv = ((const float4*)g)[tid];
    float4 bv = ((const float4*)b)[tid];
    float4 ov;
    ov.x = (v.x - mu) * r * gv.x + bv.x;
    ov.y = (v.y - mu) * r * gv.y + bv.y;
    ov.z = (v.z - mu) * r * gv.z + bv.z;
    ov.w = (v.w - mu) * r * gv.w + bv.w;
    ((float4*)(out + (size_t)tok * D_))[tid] = ov;
}

// ---------------- generic fp32 GEMM: C[M,N] = epi(A[M,K] @ W[N,K]^T + bias[N]) ----------------
// EPI: 0 none | 1 *scale | 2 sigmoid | 3 softcap | 4 += resid[m*N+n]
#define BM 128
#define BN 64
#define BK 16

template<int EPI>
__global__ void __launch_bounds__(256) gemm_epi(
    const float* __restrict__ A, const float* __restrict__ W,
    const float* __restrict__ bias, const float* __restrict__ resid,
    float* __restrict__ C, int M, int N, int K, float scale)
{
    __shared__ __align__(16) float As[BK][BM];
    __shared__ __align__(16) float Bs[BK][BN];

    int tid = threadIdx.x;
    int m0 = blockIdx.y * BM;
    int n0 = blockIdx.x * BN;
    int tx = tid & 15;          // n dir (4 cols each)
    int ty = tid >> 4;          // m dir (8 rows each)

    float acc[8][4];
    #pragma unroll
    for (int i = 0; i < 8; i++)
        #pragma unroll
        for (int j = 0; j < 4; j++) acc[i][j] = 0.f;

    int lrow = tid >> 2;        // 0..63
    int lk   = (tid & 3) * 4;   // 0,4,8,12

    for (int k0 = 0; k0 < K; k0 += BK) {
        // A tile: 128 rows x 16 k  (each thread: 2 float4)
        #pragma unroll
        for (int i = 0; i < 2; i++) {
            int row = lrow + i * 64;
            int gm = m0 + row;
            float4 av = make_float4(0.f, 0.f, 0.f, 0.f);
            if (gm < M) av = *(const float4*)(A + (size_t)gm * K + k0 + lk);
            As[lk + 0][row] = av.x; As[lk + 1][row] = av.y;
            As[lk + 2][row] = av.z; As[lk + 3][row] = av.w;
        }
        // B tile: 64 rows x 16 k
        {
            int gn = n0 + lrow;
            float4 bv = make_float4(0.f, 0.f, 0.f, 0.f);
            if (gn < N) bv = *(const float4*)(W + (size_t)gn * K + k0 + lk);
            Bs[lk + 0][lrow] = bv.x; Bs[lk + 1][lrow] = bv.y;
            Bs[lk + 2][lrow] = bv.z; Bs[lk + 3][lrow] = bv.w;
        }
        __syncthreads();

        #pragma unroll
        for (int kk = 0; kk < BK; kk++) {
            float a[8], b[4];
            *(float4*)&a[0] = *(const float4*)&As[kk][ty * 8];
            *(float4*)&a[4] = *(const float4*)&As[kk][ty * 8 + 4];
            *(float4*)&b[0] = *(const float4*)&Bs[kk][tx * 4];
            #pragma unroll
            for (int i = 0; i < 8; i++)
                #pragma unroll
                for (int j = 0; j < 4; j++) acc[i][j] = fmaf(a[i], b[j], acc[i][j]);
        }
        __syncthreads();
    }

    #pragma unroll
    for (int i = 0; i < 8; i++) {
        int gm = m0 + ty * 8 + i;
        if (gm >= M) continue;
        #pragma unroll
        for (int j = 0; j < 4; j++) {
            int gn = n0 + tx * 4 + j;
            if (gn >= N) continue;
            float v = acc[i][j] + bias[gn];
            if (EPI == 1) v *= scale;
            if (EPI == 2) v = 1.0f / (1.0f + expf(-v));
            if (EPI == 3) v = CAP * tanhf(v * (1.0f / CAP));
            if (EPI == 4) v += resid[(size_t)gm * N + gn];
            C[(size_t)gm * N + gn] = v;
        }
    }
}

// ---------------- causal conv over FEATURE axis + SiLU; one block per token ----------------
__global__ void conv_silu_kernel(const float* __restrict__ xt, const float* __restrict__ w,
                                 const float* __restrict__ cb, float* __restrict__ xc)
{
    __shared__ float row[P_];
    int tok = blockIdx.x;
    int tid = threadIdx.x;        // 256
    const float4* src = (const float4*)(xt + (size_t)tok * P_);
    float4* dstrow = (float4*)row;
    #pragma unroll
    for (int i = 0; i < 2; i++) dstrow[tid + i * 256] = src[tid + i * 256];
    __syncthreads();

    float w0 = w[0], w1 = w[1], w2 = w[2], w3 = w[3];
    float bb = cb[0];
    float* out = xc + (size_t)tok * P_;
    #pragma unroll
    for (int i = 0; i < 8; i++) {
        int p = tid * 8 + i;
        float x3 = row[p];
        float x2 = (p >= 1) ? row[p - 1] : 0.f;
        float x1 = (p >= 2) ? row[p - 2] : 0.f;
        float x0 = (p >= 3) ? row[p - 3] : 0.f;
        float v = bb + w0 * x0 + w1 * x1 + w2 * x2 + w3 * x3;
        out[p] = v / (1.0f + expf(-v));   // silu
    }
}

// ---------------- sequential mLSTM recurrence: 64 blocks (b,h), 128 threads ----------------
__global__ void __launch_bounds__(128) recur_kernel(
    const float* __restrict__ q, const float* __restrict__ k, const float* __restrict__ v,
    const float* __restrict__ ip, const float* __restrict__ fp, float* __restrict__ hs)
{
    int bh = blockIdx.x;
    int b = bh >> 3, h = bh & 7;
    int t = threadIdx.x;
    int d = t & 63, half = t >> 6;

    __shared__ __align__(16) float q_s[64], k_s[64], v_s[64];
    __shared__ float n_s[64];
    __shared__ float num_s[128];
    __shared__ float den_s[2];

    float c[32];
    #pragma unroll
    for (int j = 0; j < 32; j++) c[j] = 0.f;
    if (t < 64) n_s[t] = 1.f;
    float m = 0.f;

    size_t gbase = (size_t)b * S_ * HID_ + (size_t)h * HD_ + d;   // step stride = HID_
    size_t ifbase = (size_t)b * S_ * H_ + h;                      // step stride = H_

    float qr = 0.f, kr = 0.f, vr = 0.f;
    if (t < 64) { qr = q[gbase]; kr = k[gbase]; vr = v[gbase]; }
    float ir = ip[ifbase], fr = fp[ifbase];

    for (int s = 0; s < S_; s++) {
        if (t < 64) { q_s[t] = qr; k_s[t] = kr; v_s[t] = vr; }
        float it = ir, ft = fr;
        __syncthreads();                               // smem q/k/v ready

        // prefetch next step while we compute
        if (s + 1 < S_) {
            size_t off = gbase + (size_t)(s + 1) * HID_;
            if (t < 64) { qr = q[off]; kr = k[off]; vr = v[off]; }
            size_t ioff = ifbase + (size_t)(s + 1) * H_;
            ir = ip[ioff]; fr = fp[ioff];
        }

        float m_t = fmaxf(ft + m, it);
        float ie  = __expf(it - m_t);
        float fe  = __expf(ft - m_t + m);
        m = m_t;

        float ievd = ie * v_s[d];
        float np = 0.f;
        const float4* k4 = (const float4*)(k_s + half * 32);
        const float4* q4 = (const float4*)(q_s + half * 32);
        #pragma unroll
        for (int j = 0; j < 8; j++) {
            float4 kk = k4[j], qq = q4[j];
            float c0 = fmaf(fe, c[4 * j + 0], ievd * kk.x); c[4 * j + 0] = c0; np = fmaf(c0, qq.x, np);
            float c1 = fmaf(fe, c[4 * j + 1], ievd * kk.y); c[4 * j + 1] = c1; np = fmaf(c1, qq.y, np);
            float c2 = fmaf(fe, c[4 * j + 2], ievd * kk.z); c[4 * j + 2] = c2; np = fmaf(c2, qq.z, np);
            float c3 = fmaf(fe, c[4 * j + 3], ievd * kk.w); c[4 * j + 3] = c3; np = fmaf(c3, qq.w, np);
        }
        num_s[t] = np;

        float denp = 0.f;
        if (t < 64) {
            float nn = fmaf(fe, n_s[t], ie * k_s[t]);
            n_s[t] = nn;
            denp = nn * q_s[t];
        }
        #pragma unroll
        for (int o = 16; o > 0; o >>= 1) denp += __shfl_down_sync(0xffffffffu, denp, o);
        if (t < 64 && (t & 31) == 0) den_s[t >> 5] = denp;
        __syncthreads();                               // num_s / den ready

        if (t < 64) {
            float den = fmaxf(den_s[0] + den_s[1], 1.0f);
            hs[gbase + (size_t)s * HID_] = (num_s[t] + num_s[64 + t]) / den;
        }
    }
}

// ---------------- mix: h = o*hs, per-head LN(64), + skip, * silu(r_t) ----------------
__global__ void mix_kernel(const float* __restrict__ hs, const float* __restrict__ o,
                           const float* __restrict__ skip, const float* __restrict__ rt,
                           const float* __restrict__ mhg, const float* __restrict__ mhb,
                           float* __restrict__ u)
{
    int tok = blockIdx.x;
    int tid = threadIdx.x;          // 512
    int head = tid >> 6;
    size_t idx = (size_t)tok * HID_ + tid;

    float val = o[idx] * hs[idx];
    float s1 = val, s2 = val * val;
    for (int off = 16; off > 0; off >>= 1) {
        s1 += __shfl_down_sync(0xffffffffu, s1, off);
        s2 += __shfl_down_sync(0xffffffffu, s2, off);
    }
    __shared__ float ps1[16], ps2[16];
    int wid = tid >> 5, lane = tid & 31;
    if (lane == 0) { ps1[wid] = s1; ps2[wid] = s2; }
    __syncthreads();
    float S1 = ps1[head * 2] + ps1[head * 2 + 1];
    float S2 = ps2[head * 2] + ps2[head * 2 + 1];
    float mu = S1 * (1.0f / HD_);
    float var = S2 * (1.0f / HD_) - mu * mu;
    float r = rsqrtf(var + EPS);

    float hn = (val - mu) * r * mhg[tid] + mhb[tid];
    float rv = rt[idx];
    u[idx] = (hn + skip[idx]) * (rv / (1.0f + expf(-rv)));
}

// ---------------- host launcher ----------------
extern "C" void kernel_launch(void* const* d_in, const int* in_sizes, int n_in,
                              void* d_out, int out_size)
{
    const float* x      = (const float*)d_in[0];
    const float* ln_g   = (const float*)d_in[1];
    const float* ln_b   = (const float*)d_in[2];
    const float* mh_g   = (const float*)d_in[3];
    const float* mh_b   = (const float*)d_in[4];
    const float* W_up_l = (const float*)d_in[5];
    const float* b_up_l = (const float*)d_in[6];
    const float* W_up_r = (const float*)d_in[7];
    const float* b_up_r = (const float*)d_in[8];
    const float* W_down = (const float*)d_in[9];
    const float* b_down = (const float*)d_in[10];
    const float* conv_w = (const float*)d_in[11];
    const float* conv_b = (const float*)d_in[12];
    const float* W_skip = (const float*)d_in[13];
    const float* b_skip = (const float*)d_in[14];
    const float* W_i    = (const float*)d_in[15];
    const float* b_i    = (const float*)d_in[16];
    const float* W_f    = (const float*)d_in[17];
    const float* b_f    = (const float*)d_in[18];
    const float* W_o    = (const float*)d_in[19];
    const float* b_o    = (const float*)d_in[20];
    const float* W_q    = (const float*)d_in[21];
    const float* b_q    = (const float*)d_in[22];
    const float* W_k    = (const float*)d_in[23];
    const float* b_k    = (const float*)d_in[24];
    const float* W_v    = (const float*)d_in[25];
    const float* b_v    = (const float*)d_in[26];
    float* out = (float*)d_out;

    float* scratch = nullptr;
    cudaGetSymbolAddress((void**)&scratch, g_scratch);
    float* xn   = scratch + OFF_XN;
    float* xt   = scratch + OFF_XT;
    float* rt   = scratch + OFF_RT;
    float* xc   = scratch + OFF_XC;
    float* skip = scratch + OFF_SKIP;
    float* qb   = scratch + OFF_Q;
    float* kb   = scratch + OFF_K;
    float* vb   = scratch + OFF_V;
    float* ob   = scratch + OFF_O;
    float* ib   = scratch + OFF_I;
    float* fb   = scratch + OFF_F;
    float* hsb  = scratch + OFF_HS;
    float* ub   = scratch + OFF_U;

    // 1. layernorm
    ln_kernel<<<TOK, 256>>>(x, ln_g, ln_b, xn);

    // 2. up projections from xn
    {
        dim3 grid(P_ / BN, TOK / BM);
        gemm_epi<0><<<grid, 256>>>(xn, W_up_l, b_up_l, nullptr, xt, TOK, P_, D_, 0.f);
    }
    {
        dim3 grid(HID_ / BN, TOK / BM);
        gemm_epi<0><<<grid, 256>>>(xn, W_up_r, b_up_r, nullptr, rt, TOK, HID_, D_, 0.f);
    }

    // 3. causal feature conv + silu
    conv_silu_kernel<<<TOK, 256>>>(xt, conv_w, conv_b, xc);

    // 4. projections
    {
        dim3 grid(HID_ / BN, TOK / BM);
        gemm_epi<0><<<grid, 256>>>(xc, W_skip, b_skip, nullptr, skip, TOK, HID_, P_, 0.f);
        gemm_epi<0><<<grid, 256>>>(xc, W_q, b_q, nullptr, qb, TOK, HID_, P_, 0.f);
        gemm_epi<1><<<grid, 256>>>(xc, W_k, b_k, nullptr, kb, TOK, HID_, P_, 0.125f);
        gemm_epi<0><<<grid, 256>>>(xt, W_v, b_v, nullptr, vb, TOK, HID_, P_, 0.f);
        gemm_epi<2><<<grid, 256>>>(xt, W_o, b_o, nullptr, ob, TOK, HID_, P_, 0.f);
    }
    {
        dim3 grid(1, TOK / BM);   // N = 8
        gemm_epi<3><<<grid, 256>>>(xc, W_i, b_i, nullptr, ib, TOK, H_, P_, 0.f);
        gemm_epi<3><<<grid, 256>>>(xc, W_f, b_f, nullptr, fb, TOK, H_, P_, 0.f);
    }

    // 5. sequential recurrence over S
    recur_kernel<<<B_ * H_, 128>>>(qb, kb, vb, ib, fb, hsb);

    // 6. mix: output gate, per-head LN, skip, silu(r) gate
    mix_kernel<<<TOK, 512>>>(hsb, ob, skip, rt, mh_g, mh_b, ub);

    // 7. down projection + residual
    {
        dim3 grid(D_ / BN, TOK / BM);
        gemm_epi<4><<<grid, 256>>>(ub, W_down, b_down, x, out, TOK, D_, HID_, 0.f);
    }
}

// round 3
// speedup vs baseline: 1.7888x; 1.7888x over previous
#include <cuda_runtime.h>
#include <cuda_bf16.h>
#include <cstdint>
#include <cstddef>

// ---------------- problem constants ----------------
#define B_  8
#define S_  1024
#define D_  1024
#define H_  8
#define HD_ 64
#define HID_ 512
#define P_  2048
#define TOK (B_ * S_)          // 8192 tokens
#define EPS 1e-6f
#define CAP 15.0f

// bf16-triple K widths
#define KE_XN 3072     // 3*1024
#define KE_P  6144     // 3*2048
#define KE_UB 1536     // 3*512

// ---------------- static device scratch ----------------
__device__ __align__(128) float g_xt  [(size_t)TOK * P_];
__device__ __align__(128) float g_rt  [(size_t)TOK * HID_];
__device__ __align__(128) float g_xc  [(size_t)TOK * P_];
__device__ __align__(128) float g_skip[(size_t)TOK * HID_];
__device__ __align__(128) float g_q   [(size_t)TOK * HID_];
__device__ __align__(128) float g_k   [(size_t)TOK * HID_];
__device__ __align__(128) float g_v   [(size_t)TOK * HID_];
__device__ __align__(128) float g_o   [(size_t)TOK * HID_];
__device__ __align__(128) float g_i   [(size_t)TOK * H_];
__device__ __align__(128) float g_f   [(size_t)TOK * H_];
__device__ __align__(128) float g_hs  [(size_t)TOK * HID_];

__device__ __align__(128) __nv_bfloat16 g_xn3 [(size_t)TOK * KE_XN];
__device__ __align__(128) __nv_bfloat16 g_xt3 [(size_t)TOK * KE_P];
__device__ __align__(128) __nv_bfloat16 g_xc3 [(size_t)TOK * KE_P];
__device__ __align__(128) __nv_bfloat16 g_ub3 [(size_t)TOK * KE_UB];
__device__ __align__(128) __nv_bfloat16 g_wupl[(size_t)2048 * KE_XN];
__device__ __align__(128) __nv_bfloat16 g_wupr[(size_t)512  * KE_XN];
__device__ __align__(128) __nv_bfloat16 g_wxc [(size_t)1536 * KE_P];   // skip|q|k
__device__ __align__(128) __nv_bfloat16 g_wxt [(size_t)1024 * KE_P];   // v|o
__device__ __align__(128) __nv_bfloat16 g_wdn [(size_t)1024 * KE_UB];

// ---------------- mma.sync GEMM config ----------------
#define MTILE 128
#define NTILE 128
#define BKE   32                      // bf16 elements per k stage
#define ROWB  80                      // padded row stride in bytes (64B data + 16B pad)
#define STAGE_A (MTILE * ROWB)        // 10240
#define STAGE_B (NTILE * ROWB)        // 10240
#define STAGE_BYTES (STAGE_A + STAGE_B)
#define GSMEM (3 * STAGE_BYTES)       // 61440

__device__ __forceinline__ uint32_t smem_u32(const void* p) {
    uint32_t a;
    asm("{ .reg .u64 t; cvta.to.shared.u64 t, %1; cvt.u32.u64 %0, t; }" : "=r"(a) : "l"(p));
    return a;
}

__device__ __forceinline__ void ldsm4(uint32_t& r0, uint32_t& r1, uint32_t& r2, uint32_t& r3,
                                      uint32_t addr) {
    asm volatile("ldmatrix.sync.aligned.m8n8.x4.shared.b16 {%0,%1,%2,%3}, [%4];"
                 : "=r"(r0), "=r"(r1), "=r"(r2), "=r"(r3) : "r"(addr));
}

__device__ __forceinline__ void mma_bf16(float& c0, float& c1, float& c2, float& c3,
                                         uint32_t a0, uint32_t a1, uint32_t a2, uint32_t a3,
                                         uint32_t b0, uint32_t b1) {
    asm volatile(
        "mma.sync.aligned.m16n8k16.row.col.f32.bf16.bf16.f32 "
        "{%0,%1,%2,%3}, {%4,%5,%6,%7}, {%8,%9}, {%0,%1,%2,%3};"
        : "+f"(c0), "+f"(c1), "+f"(c2), "+f"(c3)
        : "r"(a0), "r"(a1), "r"(a2), "r"(a3), "r"(b0), "r"(b1));
}

// MODE: 0 UPL (xt fp32 + xt3 triple), 1 UPR (rt), 2 XC3 (skip|q|k*0.125),
//       3 XT2 (v | sigmoid->o), 4 DOWN (+bias+resid)
template<int MODE>
__device__ __forceinline__ void epilogue_elem(
    int gm, int n, float v,
    const float* __restrict__ b0, const float* __restrict__ b1, const float* __restrict__ b2,
    const float* __restrict__ resid,
    float* __restrict__ o0, float* __restrict__ o1, float* __restrict__ o2)
{
    if (MODE == 0) {
        v += b0[n];
        o0[(size_t)gm * 2048 + n] = v;
        __nv_bfloat16 hi = __float2bfloat16(v);
        __nv_bfloat16 lo = __float2bfloat16(v - __bfloat162float(hi));
        __nv_bfloat16* t3 = (__nv_bfloat16*)o1;
        size_t base = (size_t)gm * KE_P + n;
        t3[base] = hi; t3[base + 2048] = lo; t3[base + 4096] = hi;
    } else if (MODE == 1) {
        o0[(size_t)gm * 512 + n] = v + b0[n];
    } else if (MODE == 2) {
        int seg = n >> 9, nn = n & 511;
        float* op = seg == 0 ? o0 : (seg == 1 ? o1 : o2);
        const float* bp = seg == 0 ? b0 : (seg == 1 ? b1 : b2);
        float x = v + bp[nn];
        if (seg == 2) x *= 0.125f;
        op[(size_t)gm * 512 + nn] = x;
    } else if (MODE == 3) {
        int seg = n >> 9, nn = n & 511;
        if (seg == 0) o0[(size_t)gm * 512 + nn] = v + b0[nn];
        else {
            float x = v + b1[nn];
            o1[(size_t)gm * 512 + nn] = 1.0f / (1.0f + __expf(-x));
        }
    } else {
        o0[(size_t)gm * 1024 + n] = v + b0[n] + resid[(size_t)gm * 1024 + n];
    }
}

template<int MODE>
__global__ void __launch_bounds__(256) gemm_mma(
    const __nv_bfloat16* __restrict__ A, const __nv_bfloat16* __restrict__ W, int KE,
    const float* __restrict__ b0, const float* __restrict__ b1, const float* __restrict__ b2,
    const float* __restrict__ resid,
    float* __restrict__ o0, float* __restrict__ o1, float* __restrict__ o2)
{
    extern __shared__ __align__(128) char dsm[];
    const uint32_t sbase = smem_u32(dsm);
    const int tid = threadIdx.x;
    const int wid = tid >> 5, lane = tid & 31;
    const int warp_m = wid >> 1;            // 0..3  (32 rows each)
    const int warp_n = wid & 1;             // 0..1  (64 cols each)

    const int m0 = blockIdx.y * MTILE;
    const int n0 = blockIdx.x * NTILE;
    const int NS = KE / BKE;

    // cp.async load of one stage (A: 128 rows x 64B, B: 128 rows x 64B, padded to 80B)
    auto load_stage = [&](int ss) {
        const int buf = ss % 3;
        const uint32_t sa = sbase + buf * STAGE_BYTES;
        const int r  = tid >> 2;            // 0..63
        const int cg = tid & 3;             // 16B chunk
        {   // A rows r and r+64
            const char* gA = (const char*)(A + (size_t)(m0 + r) * KE + ss * BKE) + cg * 16;
            asm volatile("cp.async.cg.shared.global [%0], [%1], 16;"
                         :: "r"(sa + r * ROWB + cg * 16), "l"(gA));
            const char* gA2 = (const char*)(A + (size_t)(m0 + r + 64) * KE + ss * BKE) + cg * 16;
            asm volatile("cp.async.cg.shared.global [%0], [%1], 16;"
                         :: "r"(sa + (r + 64) * ROWB + cg * 16), "l"(gA2));
        }
        {   // B rows r and r+64
            const uint32_t sb = sa + STAGE_A;
            const char* gB = (const char*)(W + (size_t)(n0 + r) * KE + ss * BKE) + cg * 16;
            asm volatile("cp.async.cg.shared.global [%0], [%1], 16;"
                         :: "r"(sb + r * ROWB + cg * 16), "l"(gB));
            const char* gB2 = (const char*)(W + (size_t)(n0 + r + 64) * KE + ss * BKE) + cg * 16;
            asm volatile("cp.async.cg.shared.global [%0], [%1], 16;"
                         :: "r"(sb + (r + 64) * ROWB + cg * 16), "l"(gB2));
        }
    };

    float acc[2][8][4];
    #pragma unroll
    for (int i = 0; i < 2; i++)
        #pragma unroll
        for (int j = 0; j < 8; j++)
            #pragma unroll
            for (int c = 0; c < 4; c++) acc[i][j][c] = 0.f;

    load_stage(0);
    asm volatile("cp.async.commit_group;");
    load_stage(1);
    asm volatile("cp.async.commit_group;");

    // lane addressing for ldmatrix
    const int a_row = lane & 15;            // m within 16
    const int a_kh  = lane >> 4;            // k half (0/1) -> +16B
    const int b_row = (lane & 7) | ((lane >> 4) << 3);   // n within 16
    const int b_kh  = (lane >> 3) & 1;

    for (int s = 0; s < NS; s++) {
        asm volatile("cp.async.wait_group 1;");
        __syncthreads();

        const int ls = s + 2;
        if (ls < NS) load_stage(ls);
        asm volatile("cp.async.commit_group;");

        const uint32_t sa = sbase + (s % 3) * STAGE_BYTES;
        const uint32_t sb = sa + STAGE_A;

        #pragma unroll
        for (int ks = 0; ks < 2; ks++) {
            // A fragments: 2 m16 tiles
            uint32_t afr[2][4];
            #pragma unroll
            for (int mt = 0; mt < 2; mt++) {
                uint32_t addr = sa + (warp_m * 32 + mt * 16 + a_row) * ROWB
                              + ks * 32 + a_kh * 16;
                ldsm4(afr[mt][0], afr[mt][1], afr[mt][2], afr[mt][3], addr);
            }
            // B fragments: 4 n16 tiles (covering 64 cols)
            uint32_t bfr[4][4];
            #pragma unroll
            for (int np = 0; np < 4; np++) {
                uint32_t addr = sb + (warp_n * 64 + np * 16 + b_row) * ROWB
                              + ks * 32 + b_kh * 16;
                ldsm4(bfr[np][0], bfr[np][1], bfr[np][2], bfr[np][3], addr);
            }
            #pragma unroll
            for (int mt = 0; mt < 2; mt++)
                #pragma unroll
                for (int nt = 0; nt < 8; nt++)
                    mma_bf16(acc[mt][nt][0], acc[mt][nt][1], acc[mt][nt][2], acc[mt][nt][3],
                             afr[mt][0], afr[mt][1], afr[mt][2], afr[mt][3],
                             bfr[nt >> 1][(nt & 1) * 2], bfr[nt >> 1][(nt & 1) * 2 + 1]);
        }
        __syncthreads();
    }

    // ---- epilogue (register fragments -> global, fused bias/act) ----
    const int er = lane >> 2;               // row within 8
    const int ec = (lane & 3) * 2;          // col pair
    #pragma unroll
    for (int mt = 0; mt < 2; mt++) {
        #pragma unroll
        for (int nt = 0; nt < 8; nt++) {
            int row = m0 + warp_m * 32 + mt * 16 + er;
            int col = n0 + warp_n * 64 + nt * 8 + ec;
            epilogue_elem<MODE>(row,     col,     acc[mt][nt][0], b0, b1, b2, resid, o0, o1, o2);
            epilogue_elem<MODE>(row,     col + 1, acc[mt][nt][1], b0, b1, b2, resid, o0, o1, o2);
            epilogue_elem<MODE>(row + 8, col,     acc[mt][nt][2], b0, b1, b2, resid, o0, o1, o2);
            epilogue_elem<MODE>(row + 8, col + 1, acc[mt][nt][3], b0, b1, b2, resid, o0, o1, o2);
        }
    }
}

// ---------------- weight convert: W' = [hi | hi | lo] ----------------
__global__ void cvt_w3(const float* __restrict__ W, __nv_bfloat16* __restrict__ dst,
                       int rows, int K, int KE, int rowOff)
{
    int idx = blockIdx.x * 256 + threadIdx.x;
    if (idx >= rows * K) return;
    int r = idx / K, k = idx - r * K;
    float x = W[idx];
    __nv_bfloat16 hi = __float2bfloat16(x);
    __nv_bfloat16 lo = __float2bfloat16(x - __bfloat162float(hi));
    size_t b = (size_t)(rowOff + r) * KE + k;
    dst[b] = hi; dst[b + K] = hi; dst[b + 2 * K] = lo;
}

// ---------------- LayerNorm -> xn triple [hi | lo | hi] ----------------
__global__ void ln_kernel(const float* __restrict__ x, const float* __restrict__ g,
                          const float* __restrict__ b, __nv_bfloat16* __restrict__ out3)
{
    int tok = blockIdx.x;
    int tid = threadIdx.x;                 // 256 threads
    const float4* xr = (const float4*)(x + (size_t)tok * D_);
    float4 v = xr[tid];
    float s1 = v.x + v.y + v.z + v.w;
    float s2 = v.x * v.x + v.y * v.y + v.z * v.z + v.w * v.w;
    for (int o = 16; o > 0; o >>= 1) {
        s1 += __shfl_down_sync(0xffffffffu, s1, o);
        s2 += __shfl_down_sync(0xffffffffu, s2, o);
    }
    __shared__ float ps1[8], ps2[8];
    int wid = tid >> 5, lane = tid & 31;
    if (lane == 0) { ps1[wid] = s1; ps2[wid] = s2; }
    __syncthreads();
    float S1 = 0.f, S2 = 0.f;
    #pragma unroll
    for (int w = 0; w < 8; w++) { S1 += ps1[w]; S2 += ps2[w]; }
    float mu = S1 * (1.0f / D_);
    float var = S2 * (1.0f / D_) - mu * mu;
    float r = rsqrtf(var + EPS);

    float4 gv = ((const float4*)g)[tid];
    float4 bv = ((const float4*)b)[tid];
    float vals[4] = { (v.x - mu) * r * gv.x + bv.x, (v.y - mu) * r * gv.y + bv.y,
                      (v.z - mu) * r * gv.z + bv.z, (v.w - mu) * r * gv.w + bv.w };
    size_t base = (size_t)tok * KE_XN + tid * 4;
    #pragma unroll
    for (int i = 0; i < 4; i++) {
        __nv_bfloat16 hi = __float2bfloat16(vals[i]);
        __nv_bfloat16 lo = __float2bfloat16(vals[i] - __bfloat162float(hi));
        out3[base + i] = hi;
        out3[base + D_ + i] = lo;
        out3[base + 2 * D_ + i] = hi;
    }
}

// ---------------- causal feature conv + SiLU -> xc fp32 + xc triple ----------------
__global__ void conv_silu_kernel(const float* __restrict__ xt, const float* __restrict__ w,
                                 const float* __restrict__ cb, float* __restrict__ xc,
                                 __nv_bfloat16* __restrict__ xc3)
{
    __shared__ float row[P_];
    int tok = blockIdx.x;
    int tid = threadIdx.x;        // 256
    const float4* src = (const float4*)(xt + (size_t)tok * P_);
    float4* dstrow = (float4*)row;
    #pragma unroll
    for (int i = 0; i < 2; i++) dstrow[tid + i * 256] = src[tid + i * 256];
    __syncthreads();

    float w0 = w[0], w1 = w[1], w2 = w[2], w3 = w[3];
    float bb = cb[0];
    float* out = xc + (size_t)tok * P_;
    size_t b3 = (size_t)tok * KE_P;
    #pragma unroll
    for (int i = 0; i < 8; i++) {
        int p = tid * 8 + i;
        float x3 = row[p];
        float x2 = (p >= 1) ? row[p - 1] : 0.f;
        float x1 = (p >= 2) ? row[p - 2] : 0.f;
        float x0 = (p >= 3) ? row[p - 3] : 0.f;
        float v = bb + w0 * x0 + w1 * x1 + w2 * x2 + w3 * x3;
        v = v / (1.0f + __expf(-v));
        out[p] = v;
        __nv_bfloat16 hi = __float2bfloat16(v);
        __nv_bfloat16 lo = __float2bfloat16(v - __bfloat162float(hi));
        xc3[b3 + p] = hi;
        xc3[b3 + P_ + p] = lo;
        xc3[b3 + 2 * P_ + p] = hi;
    }
}

// ---------------- SIMT GEMM for tiny i/f projections (N=8) ----------------
#define BM 128
#define BN 64
#define BK 16
__global__ void __launch_bounds__(256) gemm_cap(
    const float* __restrict__ A, const float* __restrict__ W,
    const float* __restrict__ bias, float* __restrict__ C, int M, int N, int K)
{
    __shared__ __align__(16) float As[BK][BM];
    __shared__ __align__(16) float Bs[BK][BN];
    int tid = threadIdx.x;
    int m0 = blockIdx.y * BM;
    int tx = tid & 15, ty = tid >> 4;
    float acc[8][4];
    #pragma unroll
    for (int i = 0; i < 8; i++)
        #pragma unroll
        for (int j = 0; j < 4; j++) acc[i][j] = 0.f;
    int lrow = tid >> 2, lk = (tid & 3) * 4;
    for (int k0 = 0; k0 < K; k0 += BK) {
        #pragma unroll
        for (int i = 0; i < 2; i++) {
            int row = lrow + i * 64;
            float4 av = *(const float4*)(A + (size_t)(m0 + row) * K + k0 + lk);
            As[lk + 0][row] = av.x; As[lk + 1][row] = av.y;
            As[lk + 2][row] = av.z; As[lk + 3][row] = av.w;
        }
        {
            float4 bv = make_float4(0.f, 0.f, 0.f, 0.f);
            if (lrow < N) bv = *(const float4*)(W + (size_t)lrow * K + k0 + lk);
            Bs[lk + 0][lrow] = bv.x; Bs[lk + 1][lrow] = bv.y;
            Bs[lk + 2][lrow] = bv.z; Bs[lk + 3][lrow] = bv.w;
        }
        __syncthreads();
        #pragma unroll
        for (int kk = 0; kk < BK; kk++) {
            float a[8], b[4];
            *(float4*)&a[0] = *(const float4*)&As[kk][ty * 8];
            *(float4*)&a[4] = *(const float4*)&As[kk][ty * 8 + 4];
            *(float4*)&b[0] = *(const float4*)&Bs[kk][tx * 4];
            #pragma unroll
            for (int i = 0; i < 8; i++)
                #pragma unroll
                for (int j = 0; j < 4; j++) acc[i][j] = fmaf(a[i], b[j], acc[i][j]);
        }
        __syncthreads();
    }
    #pragma unroll
    for (int i = 0; i < 8; i++) {
        int gm = m0 + ty * 8 + i;
        #pragma unroll
        for (int j = 0; j < 4; j++) {
            int gn = tx * 4 + j;
            if (gn >= N) continue;
            float v = acc[i][j] + bias[gn];
            C[(size_t)gm * N + gn] = CAP * tanhf(v * (1.0f / CAP));
        }
    }
}

// ---------------- sequential mLSTM recurrence ----------------
__global__ void __launch_bounds__(128) recur_kernel(
    const float* __restrict__ q, const float* __restrict__ k, const float* __restrict__ v,
    const float* __restrict__ ip, const float* __restrict__ fp, float* __restrict__ hs)
{
    int bh = blockIdx.x;
    int b = bh >> 3, h = bh & 7;
    int t = threadIdx.x;
    int d = t & 63, half = t >> 6;

    __shared__ __align__(16) float q_s[64], k_s[64], v_s[64];
    __shared__ float n_s[64];
    __shared__ float num_s[128];
    __shared__ float den_s[2];

    float c[32];
    #pragma unroll
    for (int j = 0; j < 32; j++) c[j] = 0.f;
    if (t < 64) n_s[t] = 1.f;
    float m = 0.f;

    size_t gbase = (size_t)b * S_ * HID_ + (size_t)h * HD_ + d;
    size_t ifbase = (size_t)b * S_ * H_ + h;

    float qr = 0.f, kr = 0.f, vr = 0.f;
    if (t < 64) { qr = q[gbase]; kr = k[gbase]; vr = v[gbase]; }
    float ir = ip[ifbase], fr = fp[ifbase];

    for (int s = 0; s < S_; s++) {
        if (t < 64) { q_s[t] = qr; k_s[t] = kr; v_s[t] = vr; }
        float it = ir, ft = fr;
        __syncthreads();

        if (s + 1 < S_) {
            size_t off = gbase + (size_t)(s + 1) * HID_;
            if (t < 64) { qr = q[off]; kr = k[off]; vr = v[off]; }
            size_t ioff = ifbase + (size_t)(s + 1) * H_;
            ir = ip[ioff]; fr = fp[ioff];
        }

        float m_t = fmaxf(ft + m, it);
        float ie  = __expf(it - m_t);
        float fe  = __expf(ft - m_t + m);
        m = m_t;

        float ievd = ie * v_s[d];
        float np = 0.f;
        const float4* k4 = (const float4*)(k_s + half * 32);
        const float4* q4 = (const float4*)(q_s + half * 32);
        #pragma unroll
        for (int j = 0; j < 8; j++) {
            float4 kk = k4[j], qq = q4[j];
            float c0 = fmaf(fe, c[4 * j + 0], ievd * kk.x); c[4 * j + 0] = c0; np = fmaf(c0, qq.x, np);
            float c1 = fmaf(fe, c[4 * j + 1], ievd * kk.y); c[4 * j + 1] = c1; np = fmaf(c1, qq.y, np);
            float c2 = fmaf(fe, c[4 * j + 2], ievd * kk.z); c[4 * j + 2] = c2; np = fmaf(c2, qq.z, np);
            float c3 = fmaf(fe, c[4 * j + 3], ievd * kk.w); c[4 * j + 3] = c3; np = fmaf(c3, qq.w, np);
        }
        num_s[t] = np;

        float denp = 0.f;
        if (t < 64) {
            float nn = fmaf(fe, n_s[t], ie * k_s[t]);
            n_s[t] = nn;
            denp = nn * q_s[t];
        }
        #pragma unroll
        for (int o = 16; o > 0; o >>= 1) denp += __shfl_down_sync(0xffffffffu, denp, o);
        if (t < 64 && (t & 31) == 0) den_s[t >> 5] = denp;
        __syncthreads();

        if (t < 64) {
            float den = fmaxf(den_s[0] + den_s[1], 1.0f);
            hs[gbase + (size_t)s * HID_] = (num_s[t] + num_s[64 + t]) / den;
        }
    }
}

// ---------------- mix: o*hs, per-head LN, + skip, * silu(r_t) -> ub triple ----------------
__global__ void mix_kernel(const float* __restrict__ hs, const float* __restrict__ o,
                           const float* __restrict__ skip, const float* __restrict__ rt,
                           const float* __restrict__ mhg, const float* __restrict__ mhb,
                           __nv_bfloat16* __restrict__ ub3)
{
    int tok = blockIdx.x;
    int tid = threadIdx.x;          // 512
    int head = tid >> 6;
    size_t idx = (size_t)tok * HID_ + tid;

    float val = o[idx] * hs[idx];
    float s1 = val, s2 = val * val;
    for (int off = 16; off > 0; off >>= 1) {
        s1 += __shfl_down_sync(0xffffffffu, s1, off);
        s2 += __shfl_down_sync(0xffffffffu, s2, off);
    }
    __shared__ float ps1[16], ps2[16];
    int wid = tid >> 5, lane = tid & 31;
    if (lane == 0) { ps1[wid] = s1; ps2[wid] = s2; }
    __syncthreads();
    float S1 = ps1[head * 2] + ps1[head * 2 + 1];
    float S2 = ps2[head * 2] + ps2[head * 2 + 1];
    float mu = S1 * (1.0f / HD_);
    float var = S2 * (1.0f / HD_) - mu * mu;
    float r = rsqrtf(var + EPS);

    float hn = (val - mu) * r * mhg[tid] + mhb[tid];
    float rv = rt[idx];
    float u = (hn + skip[idx]) * (rv / (1.0f + __expf(-rv)));

    __nv_bfloat16 hi = __float2bfloat16(u);
    __nv_bfloat16 lo = __float2bfloat16(u - __bfloat162float(hi));
    size_t b = (size_t)tok * KE_UB + tid;
    ub3[b] = hi; ub3[b + HID_] = lo; ub3[b + 2 * HID_] = hi;
}

// ---------------- host launcher ----------------
extern "C" void kernel_launch(void* const* d_in, const int* in_sizes, int n_in,
                              void* d_out, int out_size)
{
    const float* x      = (const float*)d_in[0];
    const float* ln_g   = (const float*)d_in[1];
    const float* ln_b   = (const float*)d_in[2];
    const float* mh_g   = (const float*)d_in[3];
    const float* mh_b   = (const float*)d_in[4];
    const float* W_up_l = (const float*)d_in[5];
    const float* b_up_l = (const float*)d_in[6];
    const float* W_up_r = (const float*)d_in[7];
    const float* b_up_r = (const float*)d_in[8];
    const float* W_down = (const float*)d_in[9];
    const float* b_down = (const float*)d_in[10];
    const float* conv_w = (const float*)d_in[11];
    const float* conv_b = (const float*)d_in[12];
    const float* W_skip = (const float*)d_in[13];
    const float* b_skip = (const float*)d_in[14];
    const float* W_i    = (const float*)d_in[15];
    const float* b_i    = (const float*)d_in[16];
    const float* W_f    = (const float*)d_in[17];
    const float* b_f    = (const float*)d_in[18];
    const float* W_o    = (const float*)d_in[19];
    const float* b_o    = (const float*)d_in[20];
    const float* W_q    = (const float*)d_in[21];
    const float* b_q    = (const float*)d_in[22];
    const float* W_k    = (const float*)d_in[23];
    const float* b_k    = (const float*)d_in[24];
    const float* W_v    = (const float*)d_in[25];
    const float* b_v    = (const float*)d_in[26];
    float* out = (float*)d_out;

    float *xt, *rt, *xc, *skip, *qb, *kb, *vb, *ob, *ib, *fb, *hsb;
    __nv_bfloat16 *xn3, *xt3, *xc3, *ub3, *wupl, *wupr, *wxc, *wxt, *wdn;
    cudaGetSymbolAddress((void**)&xt,   g_xt);
    cudaGetSymbolAddress((void**)&rt,   g_rt);
    cudaGetSymbolAddress((void**)&xc,   g_xc);
    cudaGetSymbolAddress((void**)&skip, g_skip);
    cudaGetSymbolAddress((void**)&qb,   g_q);
    cudaGetSymbolAddress((void**)&kb,   g_k);
    cudaGetSymbolAddress((void**)&vb,   g_v);
    cudaGetSymbolAddress((void**)&ob,   g_o);
    cudaGetSymbolAddress((void**)&ib,   g_i);
    cudaGetSymbolAddress((void**)&fb,   g_f);
    cudaGetSymbolAddress((void**)&hsb,  g_hs);
    cudaGetSymbolAddress((void**)&xn3,  g_xn3);
    cudaGetSymbolAddress((void**)&xt3,  g_xt3);
    cudaGetSymbolAddress((void**)&xc3,  g_xc3);
    cudaGetSymbolAddress((void**)&ub3,  g_ub3);
    cudaGetSymbolAddress((void**)&wupl, g_wupl);
    cudaGetSymbolAddress((void**)&wupr, g_wupr);
    cudaGetSymbolAddress((void**)&wxc,  g_wxc);
    cudaGetSymbolAddress((void**)&wxt,  g_wxt);
    cudaGetSymbolAddress((void**)&wdn,  g_wdn);

    cudaFuncSetAttribute(gemm_mma<0>, cudaFuncAttributeMaxDynamicSharedMemorySize, GSMEM);
    cudaFuncSetAttribute(gemm_mma<1>, cudaFuncAttributeMaxDynamicSharedMemorySize, GSMEM);
    cudaFuncSetAttribute(gemm_mma<2>, cudaFuncAttributeMaxDynamicSharedMemorySize, GSMEM);
    cudaFuncSetAttribute(gemm_mma<3>, cudaFuncAttributeMaxDynamicSharedMemorySize, GSMEM);
    cudaFuncSetAttribute(gemm_mma<4>, cudaFuncAttributeMaxDynamicSharedMemorySize, GSMEM);

    // weight conversions (bf16 triple [hi|hi|lo])
    cvt_w3<<<(2048 * 1024 + 255) / 256, 256>>>(W_up_l, wupl, 2048, 1024, KE_XN, 0);
    cvt_w3<<<(512  * 1024 + 255) / 256, 256>>>(W_up_r, wupr, 512,  1024, KE_XN, 0);
    cvt_w3<<<(512  * 2048 + 255) / 256, 256>>>(W_skip, wxc,  512,  2048, KE_P, 0);
    cvt_w3<<<(512  * 2048 + 255) / 256, 256>>>(W_q,    wxc,  512,  2048, KE_P, 512);
    cvt_w3<<<(512  * 2048 + 255) / 256, 256>>>(W_k,    wxc,  512,  2048, KE_P, 1024);
    cvt_w3<<<(512  * 2048 + 255) / 256, 256>>>(W_v,    wxt,  512,  2048, KE_P, 0);
    cvt_w3<<<(512  * 2048 + 255) / 256, 256>>>(W_o,    wxt,  512,  2048, KE_P, 512);
    cvt_w3<<<(1024 * 512  + 255) / 256, 256>>>(W_down, wdn,  1024, 512,  KE_UB, 0);

    // 1. layernorm -> xn triple
    ln_kernel<<<TOK, 256>>>(x, ln_g, ln_b, xn3);

    // 2. up projections (tensor cores)
    {
        dim3 grid(2048 / NTILE, TOK / MTILE);
        gemm_mma<0><<<grid, 256, GSMEM>>>(xn3, wupl, KE_XN, b_up_l, nullptr, nullptr,
                                          nullptr, xt, (float*)xt3, nullptr);
    }
    {
        dim3 grid(512 / NTILE, TOK / MTILE);
        gemm_mma<1><<<grid, 256, GSMEM>>>(xn3, wupr, KE_XN, b_up_r, nullptr, nullptr,
                                          nullptr, rt, nullptr, nullptr);
    }

    // 3. causal conv + silu -> xc fp32 + triple
    conv_silu_kernel<<<TOK, 256>>>(xt, conv_w, conv_b, xc, xc3);

    // 4. projections (tensor cores, packed weights)
    {
        dim3 grid(1536 / NTILE, TOK / MTILE);
        gemm_mma<2><<<grid, 256, GSMEM>>>(xc3, wxc, KE_P, b_skip, b_q, b_k,
                                          nullptr, skip, qb, kb);
    }
    {
        dim3 grid(1024 / NTILE, TOK / MTILE);
        gemm_mma<3><<<grid, 256, GSMEM>>>(xt3, wxt, KE_P, b_v, b_o, nullptr,
                                          nullptr, vb, ob, nullptr);
    }

    // i/f gates (tiny, SIMT)
    {
        dim3 grid(1, TOK / BM);
        gemm_cap<<<grid, 256>>>(xc, W_i, b_i, ib, TOK, H_, P_);
        gemm_cap<<<grid, 256>>>(xc, W_f, b_f, fb, TOK, H_, P_);
    }

    // 5. sequential recurrence
    recur_kernel<<<B_ * H_, 128>>>(qb, kb, vb, ib, fb, hsb);

    // 6. mix -> ub triple
    mix_kernel<<<TOK, 512>>>(hsb, ob, skip, rt, mh_g, mh_b, ub3);

    // 7. down projection + bias + residual (tensor cores)
    {
        dim3 grid(1024 / NTILE, TOK / MTILE);
        gemm_mma<4><<<grid, 256, GSMEM>>>(ub3, wdn, KE_UB, b_down, nullptr, nullptr,
                                          x, out, nullptr, nullptr);
    }
}

// round 5
// speedup vs baseline: 2.1801x; 1.2187x over previous
#include <cuda_runtime.h>
#include <cuda_bf16.h>
#include <cstdint>
#include <cstddef>

// ---------------- problem constants ----------------
#define B_  8
#define S_  1024
#define D_  1024
#define H_  8
#define HD_ 64
#define HID_ 512
#define P_  2048
#define TOK (B_ * S_)          // 8192 tokens
#define EPS 1e-6f
#define CAP 15.0f

// bf16-triple K widths
#define KE_XN 3072     // 3*1024
#define KE_P  6144     // 3*2048
#define KE_UB 1536     // 3*512

// ---------------- static device scratch ----------------
__device__ __align__(128) float g_xt  [(size_t)TOK * P_];
__device__ __align__(128) float g_rt  [(size_t)TOK * HID_];
__device__ __align__(128) float g_xc  [(size_t)TOK * P_];
__device__ __align__(128) float g_skip[(size_t)TOK * HID_];
__device__ __align__(128) float g_q   [(size_t)TOK * HID_];
__device__ __align__(128) float g_k   [(size_t)TOK * HID_];
__device__ __align__(128) float g_v   [(size_t)TOK * HID_];
__device__ __align__(128) float g_o   [(size_t)TOK * HID_];
__device__ __align__(128) float g_i   [(size_t)TOK * H_];
__device__ __align__(128) float g_f   [(size_t)TOK * H_];
__device__ __align__(128) float g_hs  [(size_t)TOK * HID_];

__device__ __align__(128) __nv_bfloat16 g_xn3 [(size_t)TOK * KE_XN];
__device__ __align__(128) __nv_bfloat16 g_xt3 [(size_t)TOK * KE_P];
__device__ __align__(128) __nv_bfloat16 g_xc3 [(size_t)TOK * KE_P];
__device__ __align__(128) __nv_bfloat16 g_ub3 [(size_t)TOK * KE_UB];
__device__ __align__(128) __nv_bfloat16 g_wupl[(size_t)2048 * KE_XN];
__device__ __align__(128) __nv_bfloat16 g_wupr[(size_t)512  * KE_XN];
__device__ __align__(128) __nv_bfloat16 g_wxc [(size_t)1536 * KE_P];   // skip|q|k
__device__ __align__(128) __nv_bfloat16 g_wxt [(size_t)1024 * KE_P];   // v|o
__device__ __align__(128) __nv_bfloat16 g_wdn [(size_t)1024 * KE_UB];

// ---------------- mma.sync GEMM config ----------------
#define MTILE 128
#define NTILE 128
#define BKE   64                      // bf16 elements per k stage
#define ROWB  144                     // 128B data + 16B pad (bank-distinct ldsm)
#define STAGE_A (MTILE * ROWB)        // 18432
#define STAGE_B (NTILE * ROWB)        // 18432
#define STAGE_BYTES (STAGE_A + STAGE_B)
#define GSMEM (3 * STAGE_BYTES)       // 110592

__device__ __forceinline__ uint32_t smem_u32(const void* p) {
    uint32_t a;
    asm("{ .reg .u64 t; cvta.to.shared.u64 t, %1; cvt.u32.u64 %0, t; }" : "=r"(a) : "l"(p));
    return a;
}

__device__ __forceinline__ void ldsm4(uint32_t& r0, uint32_t& r1, uint32_t& r2, uint32_t& r3,
                                      uint32_t addr) {
    asm volatile("ldmatrix.sync.aligned.m8n8.x4.shared.b16 {%0,%1,%2,%3}, [%4];"
                 : "=r"(r0), "=r"(r1), "=r"(r2), "=r"(r3) : "r"(addr));
}

__device__ __forceinline__ void mma_bf16(float& c0, float& c1, float& c2, float& c3,
                                         uint32_t a0, uint32_t a1, uint32_t a2, uint32_t a3,
                                         uint32_t b0, uint32_t b1) {
    asm volatile(
        "mma.sync.aligned.m16n8k16.row.col.f32.bf16.bf16.f32 "
        "{%0,%1,%2,%3}, {%4,%5,%6,%7}, {%8,%9}, {%0,%1,%2,%3};"
        : "+f"(c0), "+f"(c1), "+f"(c2), "+f"(c3)
        : "r"(a0), "r"(a1), "r"(a2), "r"(a3), "r"(b0), "r"(b1));
}

// MODE: 0 UPL (xt fp32 + xt3 triple), 1 UPR (rt), 2 XC3 (skip|q|k*0.125),
//       3 XT2 (v | sigmoid->o), 4 DOWN (+bias+resid)
template<int MODE>
__device__ __forceinline__ void epilogue_elem(
    int gm, int n, float v,
    const float* __restrict__ b0, const float* __restrict__ b1, const float* __restrict__ b2,
    const float* __restrict__ resid,
    float* __restrict__ o0, float* __restrict__ o1, float* __restrict__ o2)
{
    if (MODE == 0) {
        v += b0[n];
        o0[(size_t)gm * 2048 + n] = v;
        __nv_bfloat16 hi = __float2bfloat16(v);
        __nv_bfloat16 lo = __float2bfloat16(v - __bfloat162float(hi));
        __nv_bfloat16* t3 = (__nv_bfloat16*)o1;
        size_t base = (size_t)gm * KE_P + n;
        t3[base] = hi; t3[base + 2048] = lo; t3[base + 4096] = hi;
    } else if (MODE == 1) {
        o0[(size_t)gm * 512 + n] = v + b0[n];
    } else if (MODE == 2) {
        int seg = n >> 9, nn = n & 511;
        float* op = seg == 0 ? o0 : (seg == 1 ? o1 : o2);
        const float* bp = seg == 0 ? b0 : (seg == 1 ? b1 : b2);
        float x = v + bp[nn];
        if (seg == 2) x *= 0.125f;
        op[(size_t)gm * 512 + nn] = x;
    } else if (MODE == 3) {
        int seg = n >> 9, nn = n & 511;
        if (seg == 0) o0[(size_t)gm * 512 + nn] = v + b0[nn];
        else {
            float x = v + b1[nn];
            o1[(size_t)gm * 512 + nn] = 1.0f / (1.0f + __expf(-x));
        }
    } else {
        o0[(size_t)gm * 1024 + n] = v + b0[n] + resid[(size_t)gm * 1024 + n];
    }
}

template<int MODE, int KE>
__global__ void __launch_bounds__(256) gemm_mma(
    const __nv_bfloat16* __restrict__ A, const __nv_bfloat16* __restrict__ W,
    const float* __restrict__ b0, const float* __restrict__ b1, const float* __restrict__ b2,
    const float* __restrict__ resid,
    float* __restrict__ o0, float* __restrict__ o1, float* __restrict__ o2)
{
    extern __shared__ __align__(128) char dsm[];
    const uint32_t sbase = smem_u32(dsm);
    const int tid = threadIdx.x;
    const int wid = tid >> 5, lane = tid & 31;
    const int warp_m = wid >> 1;            // 0..3  (32 rows each)
    const int warp_n = wid & 1;             // 0..1  (64 cols each)

    const int m0 = blockIdx.y * MTILE;
    const int n0 = blockIdx.x * NTILE;
    constexpr int NS = KE / BKE;

    // cp.async one stage: A/B each 128 rows x 128B (padded to 144B)
    auto load_stage = [&](int ss, int buf) {
        const uint32_t sa = sbase + buf * STAGE_BYTES;
        #pragma unroll
        for (int j = 0; j < 4; j++) {
            int cid = tid + j * 256;        // 0..1023
            int r = cid >> 3, cg = cid & 7;
            const char* gA = (const char*)A + ((size_t)(m0 + r) * KE + ss * BKE) * 2 + cg * 16;
            asm volatile("cp.async.cg.shared.global [%0], [%1], 16;"
                         :: "r"(sa + r * ROWB + cg * 16), "l"(gA));
            const char* gB = (const char*)W + ((size_t)(n0 + r) * KE + ss * BKE) * 2 + cg * 16;
            asm volatile("cp.async.cg.shared.global [%0], [%1], 16;"
                         :: "r"(sa + STAGE_A + r * ROWB + cg * 16), "l"(gB));
        }
    };

    float acc[2][8][4];
    #pragma unroll
    for (int i = 0; i < 2; i++)
        #pragma unroll
        for (int j = 0; j < 8; j++)
            #pragma unroll
            for (int c = 0; c < 4; c++) acc[i][j][c] = 0.f;

    load_stage(0, 0);
    asm volatile("cp.async.commit_group;");
    load_stage(1, 1);
    asm volatile("cp.async.commit_group;");

    // lane addressing for ldmatrix
    const int a_row = lane & 15;
    const int a_kh  = lane >> 4;
    const int b_row = (lane & 7) | ((lane >> 4) << 3);
    const int b_kh  = (lane >> 3) & 1;

    #pragma unroll 3
    for (int s = 0; s < NS; s++) {
        const int buf = s % 3;
        asm volatile("cp.async.wait_group 1;");
        __syncthreads();

        const int ls = s + 2;
        if (ls < NS) load_stage(ls, ls % 3);
        asm volatile("cp.async.commit_group;");

        const uint32_t sa = sbase + buf * STAGE_BYTES;
        const uint32_t sb = sa + STAGE_A;

        #pragma unroll
        for (int ks = 0; ks < 4; ks++) {
            uint32_t afr[2][4];
            #pragma unroll
            for (int mt = 0; mt < 2; mt++) {
                uint32_t addr = sa + (warp_m * 32 + mt * 16 + a_row) * ROWB
                              + ks * 32 + a_kh * 16;
                ldsm4(afr[mt][0], afr[mt][1], afr[mt][2], afr[mt][3], addr);
            }
            uint32_t bfr[4][4];
            #pragma unroll
            for (int np = 0; np < 4; np++) {
                uint32_t addr = sb + (warp_n * 64 + np * 16 + b_row) * ROWB
                              + ks * 32 + b_kh * 16;
                ldsm4(bfr[np][0], bfr[np][1], bfr[np][2], bfr[np][3], addr);
            }
            #pragma unroll
            for (int mt = 0; mt < 2; mt++)
                #pragma unroll
                for (int nt = 0; nt < 8; nt++)
                    mma_bf16(acc[mt][nt][0], acc[mt][nt][1], acc[mt][nt][2], acc[mt][nt][3],
                             afr[mt][0], afr[mt][1], afr[mt][2], afr[mt][3],
                             bfr[nt >> 1][(nt & 1) * 2], bfr[nt >> 1][(nt & 1) * 2 + 1]);
        }
        __syncthreads();
    }

    // ---- epilogue (register fragments -> global, fused bias/act) ----
    const int er = lane >> 2;
    const int ec = (lane & 3) * 2;
    #pragma unroll
    for (int mt = 0; mt < 2; mt++) {
        #pragma unroll
        for (int nt = 0; nt < 8; nt++) {
            int row = m0 + warp_m * 32 + mt * 16 + er;
            int col = n0 + warp_n * 64 + nt * 8 + ec;
            epilogue_elem<MODE>(row,     col,     acc[mt][nt][0], b0, b1, b2, resid, o0, o1, o2);
            epilogue_elem<MODE>(row,     col + 1, acc[mt][nt][1], b0, b1, b2, resid, o0, o1, o2);
            epilogue_elem<MODE>(row + 8, col,     acc[mt][nt][2], b0, b1, b2, resid, o0, o1, o2);
            epilogue_elem<MODE>(row + 8, col + 1, acc[mt][nt][3], b0, b1, b2, resid, o0, o1, o2);
        }
    }
}

// ---------------- merged weight convert: all 8 weights -> bf16 triple [hi|hi|lo] ----------------
__global__ void cvt_all(const float* __restrict__ Wupl, const float* __restrict__ Wupr,
                        const float* __restrict__ Wskip, const float* __restrict__ Wq,
                        const float* __restrict__ Wk, const float* __restrict__ Wv,
                        const float* __restrict__ Wo, const float* __restrict__ Wdn,
                        __nv_bfloat16* __restrict__ wupl, __nv_bfloat16* __restrict__ wupr,
                        __nv_bfloat16* __restrict__ wxc, __nv_bfloat16* __restrict__ wxt,
                        __nv_bfloat16* __restrict__ wdn)
{
    int idx = blockIdx.x * 256 + threadIdx.x;
    const float* src; __nv_bfloat16* dst; int K, KE, rowOff, local;
    if      (idx < 2097152) { src = Wupl;  dst = wupl; K = 1024; KE = KE_XN; rowOff = 0;    local = idx; }
    else if (idx < 2621440) { src = Wupr;  dst = wupr; K = 1024; KE = KE_XN; rowOff = 0;    local = idx - 2097152; }
    else if (idx < 3670016) { src = Wskip; dst = wxc;  K = 2048; KE = KE_P;  rowOff = 0;    local = idx - 2621440; }
    else if (idx < 4718592) { src = Wq;    dst = wxc;  K = 2048; KE = KE_P;  rowOff = 512;  local = idx - 3670016; }
    else if (idx < 5767168) { src = Wk;    dst = wxc;  K = 2048; KE = KE_P;  rowOff = 1024; local = idx - 4718592; }
    else if (idx < 6815744) { src = Wv;    dst = wxt;  K = 2048; KE = KE_P;  rowOff = 0;    local = idx - 5767168; }
    else if (idx < 7864320) { src = Wo;    dst = wxt;  K = 2048; KE = KE_P;  rowOff = 512;  local = idx - 6815744; }
    else if (idx < 8388608) { src = Wdn;   dst = wdn;  K = 512;  KE = KE_UB; rowOff = 0;    local = idx - 7864320; }
    else return;
    int r = local / K, k = local - r * K;
    float x = src[local];
    __nv_bfloat16 hi = __float2bfloat16(x);
    __nv_bfloat16 lo = __float2bfloat16(x - __bfloat162float(hi));
    size_t b = (size_t)(rowOff + r) * KE + k;
    dst[b] = hi; dst[b + K] = hi; dst[b + 2 * K] = lo;
}

// ---------------- LayerNorm -> xn triple [hi | lo | hi] ----------------
__global__ void ln_kernel(const float* __restrict__ x, const float* __restrict__ g,
                          const float* __restrict__ b, __nv_bfloat16* __restrict__ out3)
{
    int tok = blockIdx.x;
    int tid = threadIdx.x;                 // 256 threads
    const float4* xr = (const float4*)(x + (size_t)tok * D_);
    float4 v = xr[tid];
    float s1 = v.x + v.y + v.z + v.w;
    float s2 = v.x * v.x + v.y * v.y + v.z * v.z + v.w * v.w;
    for (int o = 16; o > 0; o >>= 1) {
        s1 += __shfl_down_sync(0xffffffffu, s1, o);
        s2 += __shfl_down_sync(0xffffffffu, s2, o);
    }
    __shared__ float ps1[8], ps2[8];
    int wid = tid >> 5, lane = tid & 31;
    if (lane == 0) { ps1[wid] = s1; ps2[wid] = s2; }
    __syncthreads();
    float S1 = 0.f, S2 = 0.f;
    #pragma unroll
    for (int w = 0; w < 8; w++) { S1 += ps1[w]; S2 += ps2[w]; }
    float mu = S1 * (1.0f / D_);
    float var = S2 * (1.0f / D_) - mu * mu;
    float r = rsqrtf(var + EPS);

    float4 gv = ((const float4*)g)[tid];
    float4 bv = ((const float4*)b)[tid];
    float vals[4] = { (v.x - mu) * r * gv.x + bv.x, (v.y - mu) * r * gv.y + bv.y,
                      (v.z - mu) * r * gv.z + bv.z, (v.w - mu) * r * gv.w + bv.w };
    size_t base = (size_t)tok * KE_XN + tid * 4;
    #pragma unroll
    for (int i = 0; i < 4; i++) {
        __nv_bfloat16 hi = __float2bfloat16(vals[i]);
        __nv_bfloat16 lo = __float2bfloat16(vals[i] - __bfloat162float(hi));
        out3[base + i] = hi;
        out3[base + D_ + i] = lo;
        out3[base + 2 * D_ + i] = hi;
    }
}

// ---------------- causal feature conv + SiLU -> xc fp32 + xc triple ----------------
__global__ void conv_silu_kernel(const float* __restrict__ xt, const float* __restrict__ w,
                                 const float* __restrict__ cb, float* __restrict__ xc,
                                 __nv_bfloat16* __restrict__ xc3)
{
    __shared__ float row[P_];
    int tok = blockIdx.x;
    int tid = threadIdx.x;        // 256
    const float4* src = (const float4*)(xt + (size_t)tok * P_);
    float4* dstrow = (float4*)row;
    #pragma unroll
    for (int i = 0; i < 2; i++) dstrow[tid + i * 256] = src[tid + i * 256];
    __syncthreads();

    float w0 = w[0], w1 = w[1], w2 = w[2], w3 = w[3];
    float bb = cb[0];
    float* out = xc + (size_t)tok * P_;
    size_t b3 = (size_t)tok * KE_P;
    #pragma unroll
    for (int i = 0; i < 8; i++) {
        int p = tid * 8 + i;
        float x3 = row[p];
        float x2 = (p >= 1) ? row[p - 1] : 0.f;
        float x1 = (p >= 2) ? row[p - 2] : 0.f;
        float x0 = (p >= 3) ? row[p - 3] : 0.f;
        float v = bb + w0 * x0 + w1 * x1 + w2 * x2 + w3 * x3;
        v = v / (1.0f + __expf(-v));
        out[p] = v;
        __nv_bfloat16 hi = __float2bfloat16(v);
        __nv_bfloat16 lo = __float2bfloat16(v - __bfloat162float(hi));
        xc3[b3 + p] = hi;
        xc3[b3 + P_ + p] = lo;
        xc3[b3 + 2 * P_ + p] = hi;
    }
}

// ---------------- fused i/f projections (N=16, softcap) ----------------
#define BM 128
#define BK 16
__global__ void __launch_bounds__(256) gemm_capif(
    const float* __restrict__ A, const float* __restrict__ Wi, const float* __restrict__ Wf,
    const float* __restrict__ bi, const float* __restrict__ bf,
    float* __restrict__ Ci, float* __restrict__ Cf, int K)
{
    __shared__ __align__(16) float As[BK][BM];
    __shared__ __align__(16) float Bs[BK][16];
    int tid = threadIdx.x;
    int m0 = blockIdx.y * BM;
    int tx = tid & 3;               // 4 col groups of 4
    int ty = tid >> 2;              // 64 row groups of 2
    float acc[2][4];
    #pragma unroll
    for (int i = 0; i < 2; i++)
        #pragma unroll
        for (int j = 0; j < 4; j++) acc[i][j] = 0.f;
    int lrow = tid >> 2, lk = (tid & 3) * 4;
    for (int k0 = 0; k0 < K; k0 += BK) {
        #pragma unroll
        for (int i = 0; i < 2; i++) {
            int row = lrow + i * 64;
            float4 av = *(const float4*)(A + (size_t)(m0 + row) * K + k0 + lk);
            As[lk + 0][row] = av.x; As[lk + 1][row] = av.y;
            As[lk + 2][row] = av.z; As[lk + 3][row] = av.w;
        }
        if (lrow < 16) {
            const float* Wp = (lrow < 8) ? Wi + (size_t)lrow * K : Wf + (size_t)(lrow - 8) * K;
            float4 bv = *(const float4*)(Wp + k0 + lk);
            Bs[lk + 0][lrow] = bv.x; Bs[lk + 1][lrow] = bv.y;
            Bs[lk + 2][lrow] = bv.z; Bs[lk + 3][lrow] = bv.w;
        }
        __syncthreads();
        #pragma unroll
        for (int kk = 0; kk < BK; kk++) {
            float a0 = As[kk][ty * 2], a1 = As[kk][ty * 2 + 1];
            float b[4];
            *(float4*)&b[0] = *(const float4*)&Bs[kk][tx * 4];
            #pragma unroll
            for (int j = 0; j < 4; j++) {
                acc[0][j] = fmaf(a0, b[j], acc[0][j]);
                acc[1][j] = fmaf(a1, b[j], acc[1][j]);
            }
        }
        __syncthreads();
    }
    #pragma unroll
    for (int i = 0; i < 2; i++) {
        int gm = m0 + ty * 2 + i;
        #pragma unroll
        for (int j = 0; j < 4; j++) {
            int gn = tx * 4 + j;
            float* Cp = (gn < 8) ? Ci : Cf;
            const float* bp = (gn < 8) ? bi : bf;
            int nn = gn & 7;
            float v = acc[i][j] + bp[nn];
            Cp[(size_t)gm * H_ + nn] = CAP * tanhf(v * (1.0f / CAP));
        }
    }
}

// ---------------- sequential mLSTM recurrence ----------------
__global__ void __launch_bounds__(128) recur_kernel(
    const float* __restrict__ q, const float* __restrict__ k, const float* __restrict__ v,
    const float* __restrict__ ip, const float* __restrict__ fp, float* __restrict__ hs)
{
    int bh = blockIdx.x;
    int b = bh >> 3, h = bh & 7;
    int t = threadIdx.x;
    int d = t & 63, half = t >> 6;

    __shared__ __align__(16) float q_s[64], k_s[64], v_s[64];
    __shared__ float n_s[64];
    __shared__ float num_s[128];
    __shared__ float den_s[2];

    float c[32];
    #pragma unroll
    for (int j = 0; j < 32; j++) c[j] = 0.f;
    if (t < 64) n_s[t] = 1.f;
    float m = 0.f;

    size_t gbase = (size_t)b * S_ * HID_ + (size_t)h * HD_ + d;
    size_t ifbase = (size_t)b * S_ * H_ + h;

    float qr = 0.f, kr = 0.f, vr = 0.f;
    if (t < 64) { qr = q[gbase]; kr = k[gbase]; vr = v[gbase]; }
    float ir = ip[ifbase], fr = fp[ifbase];

    for (int s = 0; s < S_; s++) {
        if (t < 64) { q_s[t] = qr; k_s[t] = kr; v_s[t] = vr; }
        float it = ir, ft = fr;
        __syncthreads();

        if (s + 1 < S_) {
            size_t off = gbase + (size_t)(s + 1) * HID_;
            if (t < 64) { qr = q[off]; kr = k[off]; vr = v[off]; }
            size_t ioff = ifbase + (size_t)(s + 1) * H_;
            ir = ip[ioff]; fr = fp[ioff];
        }

        float m_t = fmaxf(ft + m, it);
        float ie  = __expf(it - m_t);
        float fe  = __expf(ft - m_t + m);
        m = m_t;

        float ievd = ie * v_s[d];
        float np0 = 0.f, np1 = 0.f, np2 = 0.f, np3 = 0.f;
        const float4* k4 = (const float4*)(k_s + half * 32);
        const float4* q4 = (const float4*)(q_s + half * 32);
        #pragma unroll
        for (int j = 0; j < 8; j++) {
            float4 kk = k4[j], qq = q4[j];
            float c0 = fmaf(fe, c[4 * j + 0], ievd * kk.x); c[4 * j + 0] = c0; np0 = fmaf(c0, qq.x, np0);
            float c1 = fmaf(fe, c[4 * j + 1], ievd * kk.y); c[4 * j + 1] = c1; np1 = fmaf(c1, qq.y, np1);
            float c2 = fmaf(fe, c[4 * j + 2], ievd * kk.z); c[4 * j + 2] = c2; np2 = fmaf(c2, qq.z, np2);
            float c3 = fmaf(fe, c[4 * j + 3], ievd * kk.w); c[4 * j + 3] = c3; np3 = fmaf(c3, qq.w, np3);
        }
        num_s[t] = (np0 + np1) + (np2 + np3);

        float denp = 0.f;
        if (t < 64) {
            float nn = fmaf(fe, n_s[t], ie * k_s[t]);
            n_s[t] = nn;
            denp = nn * q_s[t];
        }
        #pragma unroll
        for (int o = 16; o > 0; o >>= 1) denp += __shfl_down_sync(0xffffffffu, denp, o);
        if (t < 64 && (t & 31) == 0) den_s[t >> 5] = denp;
        __syncthreads();

        if (t < 64) {
            float den = fmaxf(den_s[0] + den_s[1], 1.0f);
            hs[gbase + (size_t)s * HID_] = (num_s[t] + num_s[64 + t]) / den;
        }
    }
}

// ---------------- mix: o*hs, per-head LN, + skip, * silu(r_t) -> ub triple ----------------
__global__ void mix_kernel(const float* __restrict__ hs, const float* __restrict__ o,
                           const float* __restrict__ skip, const float* __restrict__ rt,
                           const float* __restrict__ mhg, const float* __restrict__ mhb,
                           __nv_bfloat16* __restrict__ ub3)
{
    int tok = blockIdx.x;
    int tid = threadIdx.x;          // 512
    int head = tid >> 6;
    size_t idx = (size_t)tok * HID_ + tid;

    float val = o[idx] * hs[idx];
    float s1 = val, s2 = val * val;
    for (int off = 16; off > 0; off >>= 1) {
        s1 += __shfl_down_sync(0xffffffffu, s1, off);
        s2 += __shfl_down_sync(0xffffffffu, s2, off);
    }
    __shared__ float ps1[16], ps2[16];
    int wid = tid >> 5, lane = tid & 31;
    if (lane == 0) { ps1[wid] = s1; ps2[wid] = s2; }
    __syncthreads();
    float S1 = ps1[head * 2] + ps1[head * 2 + 1];
    float S2 = ps2[head * 2] + ps2[head * 2 + 1];
    float mu = S1 * (1.0f / HD_);
    float var = S2 * (1.0f / HD_) - mu * mu;
    float r = rsqrtf(var + EPS);

    float hn = (val - mu) * r * mhg[tid] + mhb[tid];
    float rv = rt[idx];
    float u = (hn + skip[idx]) * (rv / (1.0f + __expf(-rv)));

    __nv_bfloat16 hi = __float2bfloat16(u);
    __nv_bfloat16 lo = __float2bfloat16(u - __bfloat162float(hi));
    size_t b = (size_t)tok * KE_UB + tid;
    ub3[b] = hi; ub3[b + HID_] = lo; ub3[b + 2 * HID_] = hi;
}

// ---------------- host launcher ----------------
extern "C" void kernel_launch(void* const* d_in, const int* in_sizes, int n_in,
                              void* d_out, int out_size)
{
    const float* x      = (const float*)d_in[0];
    const float* ln_g   = (const float*)d_in[1];
    const float* ln_b   = (const float*)d_in[2];
    const float* mh_g   = (const float*)d_in[3];
    const float* mh_b   = (const float*)d_in[4];
    const float* W_up_l = (const float*)d_in[5];
    const float* b_up_l = (const float*)d_in[6];
    const float* W_up_r = (const float*)d_in[7];
    const float* b_up_r = (const float*)d_in[8];
    const float* W_down = (const float*)d_in[9];
    const float* b_down = (const float*)d_in[10];
    const float* conv_w = (const float*)d_in[11];
    const float* conv_b = (const float*)d_in[12];
    const float* W_skip = (const float*)d_in[13];
    const float* b_skip = (const float*)d_in[14];
    const float* W_i    = (const float*)d_in[15];
    const float* b_i    = (const float*)d_in[16];
    const float* W_f    = (const float*)d_in[17];
    const float* b_f    = (const float*)d_in[18];
    const float* W_o    = (const float*)d_in[19];
    const float* b_o    = (const float*)d_in[20];
    const float* W_q    = (const float*)d_in[21];
    const float* b_q    = (const float*)d_in[22];
    const float* W_k    = (const float*)d_in[23];
    const float* b_k    = (const float*)d_in[24];
    const float* W_v    = (const float*)d_in[25];
    const float* b_v    = (const float*)d_in[26];
    float* out = (float*)d_out;

    float *xt, *rt, *xc, *skip, *qb, *kb, *vb, *ob, *ib, *fb, *hsb;
    __nv_bfloat16 *xn3, *xt3, *xc3, *ub3, *wupl, *wupr, *wxc, *wxt, *wdn;
    cudaGetSymbolAddress((void**)&xt,   g_xt);
    cudaGetSymbolAddress((void**)&rt,   g_rt);
    cudaGetSymbolAddress((void**)&xc,   g_xc);
    cudaGetSymbolAddress((void**)&skip, g_skip);
    cudaGetSymbolAddress((void**)&qb,   g_q);
    cudaGetSymbolAddress((void**)&kb,   g_k);
    cudaGetSymbolAddress((void**)&vb,   g_v);
    cudaGetSymbolAddress((void**)&ob,   g_o);
    cudaGetSymbolAddress((void**)&ib,   g_i);
    cudaGetSymbolAddress((void**)&fb,   g_f);
    cudaGetSymbolAddress((void**)&hsb,  g_hs);
    cudaGetSymbolAddress((void**)&xn3,  g_xn3);
    cudaGetSymbolAddress((void**)&xt3,  g_xt3);
    cudaGetSymbolAddress((void**)&xc3,  g_xc3);
    cudaGetSymbolAddress((void**)&ub3,  g_ub3);
    cudaGetSymbolAddress((void**)&wupl, g_wupl);
    cudaGetSymbolAddress((void**)&wupr, g_wupr);
    cudaGetSymbolAddress((void**)&wxc,  g_wxc);
    cudaGetSymbolAddress((void**)&wxt,  g_wxt);
    cudaGetSymbolAddress((void**)&wdn,  g_wdn);

    cudaFuncSetAttribute((const void*)gemm_mma<0, KE_XN>, cudaFuncAttributeMaxDynamicSharedMemorySize, GSMEM);
    cudaFuncSetAttribute((const void*)gemm_mma<1, KE_XN>, cudaFuncAttributeMaxDynamicSharedMemorySize, GSMEM);
    cudaFuncSetAttribute((const void*)gemm_mma<2, KE_P>,  cudaFuncAttributeMaxDynamicSharedMemorySize, GSMEM);
    cudaFuncSetAttribute((const void*)gemm_mma<3, KE_P>,  cudaFuncAttributeMaxDynamicSharedMemorySize, GSMEM);
    cudaFuncSetAttribute((const void*)gemm_mma<4, KE_UB>, cudaFuncAttributeMaxDynamicSharedMemorySize, GSMEM);

    // [0] merged weight conversion
    cvt_all<<<8388608 / 256, 256>>>(W_up_l, W_up_r, W_skip, W_q, W_k, W_v, W_o, W_down,
                                    wupl, wupr, wxc, wxt, wdn);

    // [1] layernorm -> xn triple
    ln_kernel<<<TOK, 256>>>(x, ln_g, ln_b, xn3);

    // [2] up_l (tensor cores)
    {
        dim3 grid(2048 / NTILE, TOK / MTILE);
        gemm_mma<0, KE_XN><<<grid, 256, GSMEM>>>(xn3, wupl, b_up_l, nullptr, nullptr,
                                                 nullptr, xt, (float*)xt3, nullptr);
    }
    // [3] up_r
    {
        dim3 grid(512 / NTILE, TOK / MTILE);
        gemm_mma<1, KE_XN><<<grid, 256, GSMEM>>>(xn3, wupr, b_up_r, nullptr, nullptr,
                                                 nullptr, rt, nullptr, nullptr);
    }

    // [4] causal conv + silu
    conv_silu_kernel<<<TOK, 256>>>(xt, conv_w, conv_b, xc, xc3);

    // [5] skip|q|k (biggest GEMM — profiled by ncu -s 5)
    {
        dim3 grid(1536 / NTILE, TOK / MTILE);
        gemm_mma<2, KE_P><<<grid, 256, GSMEM>>>(xc3, wxc, b_skip, b_q, b_k,
                                                nullptr, skip, qb, kb);
    }
    // [6] v|o
    {
        dim3 grid(1024 / NTILE, TOK / MTILE);
        gemm_mma<3, KE_P><<<grid, 256, GSMEM>>>(xt3, wxt, b_v, b_o, nullptr,
                                                nullptr, vb, ob, nullptr);
    }

    // [7] i/f gates fused
    {
        dim3 grid(1, TOK / BM);
        gemm_capif<<<grid, 256>>>(xc, W_i, W_f, b_i, b_f, ib, fb, P_);
    }

    // [8] sequential recurrence
    recur_kernel<<<B_ * H_, 128>>>(qb, kb, vb, ib, fb, hsb);

    // [9] mix -> ub triple
    mix_kernel<<<TOK, 512>>>(hsb, ob, skip, rt, mh_g, mh_b, ub3);

    // [10] down projection + bias + residual
    {
        dim3 grid(1024 / NTILE, TOK / MTILE);
        gemm_mma<4, KE_UB><<<grid, 256, GSMEM>>>(ub3, wdn, b_down, nullptr, nullptr,
                                                 x, out, nullptr, nullptr);
    }
}

// round 6
// speedup vs baseline: 2.7414x; 1.2575x over previous
#include <cuda_runtime.h>
#include <cuda_bf16.h>
#include <cstdint>
#include <cstddef>

// ---------------- problem constants ----------------
#define B_  8
#define S_  1024
#define D_  1024
#define H_  8
#define HD_ 64
#define HID_ 512
#define P_  2048
#define TOK (B_ * S_)          // 8192 tokens
#define EPS 1e-6f
#define CAP 15.0f

// W (triple) K widths; A (dual) widths are 2/3 of these
#define KE_XN 3072
#define KE_P  6144
#define KE_UB 1536

// ---------------- static device scratch ----------------
__device__ __align__(128) float g_rt  [(size_t)TOK * HID_];
__device__ __align__(128) float g_skip[(size_t)TOK * HID_];
__device__ __align__(128) float g_q   [(size_t)TOK * HID_];
__device__ __align__(128) float g_k   [(size_t)TOK * HID_];
__device__ __align__(128) float g_v   [(size_t)TOK * HID_];
__device__ __align__(128) float g_o   [(size_t)TOK * HID_];
__device__ __align__(128) float g_i   [(size_t)TOK * H_];
__device__ __align__(128) float g_f   [(size_t)TOK * H_];
__device__ __align__(128) float g_hs  [(size_t)TOK * HID_];

__device__ __align__(128) __nv_bfloat16 g_xn2 [(size_t)TOK * 2048];  // [hi|lo] of xn
__device__ __align__(128) __nv_bfloat16 g_xt2 [(size_t)TOK * 4096];  // [hi|lo] of x_t
__device__ __align__(128) __nv_bfloat16 g_xc2 [(size_t)TOK * 4096];  // [hi|lo] of x_c
__device__ __align__(128) __nv_bfloat16 g_ub2 [(size_t)TOK * 1024];  // [hi|lo] of u
__device__ __align__(128) __nv_bfloat16 g_wup [(size_t)2560 * KE_XN];   // up_l|up_r
__device__ __align__(128) __nv_bfloat16 g_wxc [(size_t)1664 * KE_P];    // skip|q|k|i|f|pad0
__device__ __align__(128) __nv_bfloat16 g_wxt [(size_t)1024 * KE_P];    // v|o
__device__ __align__(128) __nv_bfloat16 g_wdn [(size_t)1024 * KE_UB];

// ---------------- mma.sync GEMM config ----------------
#define MTILE 128
#define NTILE 128
#define BKE   64
#define ROWB  144
#define STAGE_A (MTILE * ROWB)
#define STAGE_B (NTILE * ROWB)
#define STAGE_BYTES (STAGE_A + STAGE_B)
#define GSMEM (3 * STAGE_BYTES)       // 110592

__device__ __forceinline__ uint32_t smem_u32(const void* p) {
    uint32_t a;
    asm("{ .reg .u64 t; cvta.to.shared.u64 t, %1; cvt.u32.u64 %0, t; }" : "=r"(a) : "l"(p));
    return a;
}

__device__ __forceinline__ void ldsm4(uint32_t& r0, uint32_t& r1, uint32_t& r2, uint32_t& r3,
                                      uint32_t addr) {
    asm volatile("ldmatrix.sync.aligned.m8n8.x4.shared.b16 {%0,%1,%2,%3}, [%4];"
                 : "=r"(r0), "=r"(r1), "=r"(r2), "=r"(r3) : "r"(addr));
}

__device__ __forceinline__ void mma_bf16(float& c0, float& c1, float& c2, float& c3,
                                         uint32_t a0, uint32_t a1, uint32_t a2, uint32_t a3,
                                         uint32_t b0, uint32_t b1) {
    asm volatile(
        "mma.sync.aligned.m16n8k16.row.col.f32.bf16.bf16.f32 "
        "{%0,%1,%2,%3}, {%4,%5,%6,%7}, {%8,%9}, {%0,%1,%2,%3};"
        : "+f"(c0), "+f"(c1), "+f"(c2), "+f"(c3)
        : "r"(a0), "r"(a1), "r"(a2), "r"(a3), "r"(b0), "r"(b1));
}

__device__ __forceinline__ void split2(float v, __nv_bfloat16& hi, __nv_bfloat16& lo) {
    hi = __float2bfloat16(v);
    lo = __float2bfloat16(v - __bfloat162float(hi));
}

// MODE: 0 UP (n<2048: xt2 dual | n>=2048: rt fp32)
//       2 XC (skip|q|k*0.125|i softcap|f softcap)
//       3 XT (v | sigmoid->o)
//       4 DOWN (+bias+resid)
template<int MODE>
__device__ __forceinline__ void epi_pair(
    int gm, int col, float v0, float v1,
    const float* __restrict__ b0, const float* __restrict__ b1, const float* __restrict__ b2,
    const float* __restrict__ b3, const float* __restrict__ b4,
    const float* __restrict__ resid,
    float* __restrict__ o0, float* __restrict__ o1, float* __restrict__ o2,
    float* __restrict__ o3, float* __restrict__ o4)
{
    if (MODE == 0) {
        if (col < 2048) {
            v0 += b0[col]; v1 += b0[col + 1];
            __nv_bfloat16 h0, l0, h1, l1;
            split2(v0, h0, l0); split2(v1, h1, l1);
            __nv_bfloat16* xt2 = (__nv_bfloat16*)o0;
            size_t base = (size_t)gm * 4096 + col;
            *(__nv_bfloat162*)(xt2 + base)        = __nv_bfloat162(h0, h1);
            *(__nv_bfloat162*)(xt2 + base + 2048) = __nv_bfloat162(l0, l1);
        } else {
            int nn = col - 2048;
            float2 r = make_float2(v0 + b1[nn], v1 + b1[nn + 1]);
            *(float2*)(o1 + (size_t)gm * 512 + nn) = r;
        }
    } else if (MODE == 2) {
        if (col < 1536) {
            int seg = col >> 9, nn = col & 511;
            float* op = seg == 0 ? o0 : (seg == 1 ? o1 : o2);
            const float* bp = seg == 0 ? b0 : (seg == 1 ? b1 : b2);
            float s = (seg == 2) ? 0.125f : 1.0f;
            float2 r = make_float2((v0 + bp[nn]) * s, (v1 + bp[nn + 1]) * s);
            *(float2*)(op + (size_t)gm * 512 + nn) = r;
        } else {
            int nn = col - 1536;
            if (nn < 16) {
                #pragma unroll
                for (int e = 0; e < 2; e++) {
                    int n = nn + e;
                    float v = e == 0 ? v0 : v1;
                    if (n < 8)       o3[(size_t)gm * H_ + n]     = CAP * tanhf((v + b3[n]) * (1.0f / CAP));
                    else if (n < 16) o4[(size_t)gm * H_ + n - 8] = CAP * tanhf((v + b4[n - 8]) * (1.0f / CAP));
                }
            }
        }
    } else if (MODE == 3) {
        int seg = col >> 9, nn = col & 511;
        if (seg == 0) {
            float2 r = make_float2(v0 + b0[nn], v1 + b0[nn + 1]);
            *(float2*)(o0 + (size_t)gm * 512 + nn) = r;
        } else {
            float x0 = v0 + b1[nn], x1 = v1 + b1[nn + 1];
            float2 r = make_float2(1.0f / (1.0f + __expf(-x0)), 1.0f / (1.0f + __expf(-x1)));
            *(float2*)(o1 + (size_t)gm * 512 + nn) = r;
        }
    } else {
        float2 rr = *(const float2*)(resid + (size_t)gm * 1024 + col);
        float2 r = make_float2(v0 + b0[col] + rr.x, v1 + b0[col + 1] + rr.y);
        *(float2*)(o0 + (size_t)gm * 1024 + col) = r;
    }
}

template<int MODE, int KE>
__global__ void __launch_bounds__(256) gemm_mma(
    const __nv_bfloat16* __restrict__ A, const __nv_bfloat16* __restrict__ W,
    const float* __restrict__ b0, const float* __restrict__ b1, const float* __restrict__ b2,
    const float* __restrict__ b3, const float* __restrict__ b4,
    const float* __restrict__ resid,
    float* __restrict__ o0, float* __restrict__ o1, float* __restrict__ o2,
    float* __restrict__ o3, float* __restrict__ o4)
{
    extern __shared__ __align__(128) char dsm[];
    const uint32_t sbase = smem_u32(dsm);
    const int tid = threadIdx.x;
    const int wid = tid >> 5, lane = tid & 31;
    const int warp_m = wid >> 1;
    const int warp_n = wid & 1;

    const int m0 = blockIdx.y * MTILE;
    const int n0 = blockIdx.x * NTILE;
    constexpr int NS = KE / BKE;
    constexpr int KB = KE / 3 / BKE;        // stages per K-block
    constexpr int AW = (KE / 3) * 2;        // A dual width in elements

    auto load_stage = [&](int ss, int buf) {
        const int ass = (ss >= 2 * KB) ? ss - 2 * KB : ss;   // third block re-reads hi
        const uint32_t sa = sbase + buf * STAGE_BYTES;
        #pragma unroll
        for (int j = 0; j < 4; j++) {
            int cid = tid + j * 256;
            int r = cid >> 3, cg = cid & 7;
            const char* gA = (const char*)A + ((size_t)(m0 + r) * AW + ass * BKE) * 2 + cg * 16;
            asm volatile("cp.async.cg.shared.global [%0], [%1], 16;"
                         :: "r"(sa + r * ROWB + cg * 16), "l"(gA));
            const char* gB = (const char*)W + ((size_t)(n0 + r) * KE + ss * BKE) * 2 + cg * 16;
            asm volatile("cp.async.cg.shared.global [%0], [%1], 16;"
                         :: "r"(sa + STAGE_A + r * ROWB + cg * 16), "l"(gB));
        }
    };

    float acc[2][8][4];
    #pragma unroll
    for (int i = 0; i < 2; i++)
        #pragma unroll
        for (int j = 0; j < 8; j++)
            #pragma unroll
            for (int c = 0; c < 4; c++) acc[i][j][c] = 0.f;

    load_stage(0, 0);
    asm volatile("cp.async.commit_group;");
    load_stage(1, 1);
    asm volatile("cp.async.commit_group;");

    const int a_row = lane & 15;
    const int a_kh  = lane >> 4;
    const int b_row = (lane & 7) | ((lane >> 4) << 3);
    const int b_kh  = (lane >> 3) & 1;

    uint32_t fa[2][2][4];     // [buf][mt][4]
    uint32_t fb[2][4][4];     // [buf][np][4]

    #pragma unroll 3
    for (int s = 0; s < NS; s++) {
        const int buf = s % 3;
        asm volatile("cp.async.wait_group 1;");
        __syncthreads();      // stage s visible; prior-iter ldsm done before overwrite below

        const int ls = s + 2;
        if (ls < NS) load_stage(ls, ls % 3);
        asm volatile("cp.async.commit_group;");

        const uint32_t sa = sbase + buf * STAGE_BYTES;
        const uint32_t sb = sa + STAGE_A;

        // prime ks=0 fragments
        #pragma unroll
        for (int mt = 0; mt < 2; mt++) {
            uint32_t addr = sa + (warp_m * 32 + mt * 16 + a_row) * ROWB + a_kh * 16;
            ldsm4(fa[0][mt][0], fa[0][mt][1], fa[0][mt][2], fa[0][mt][3], addr);
        }
        #pragma unroll
        for (int np = 0; np < 4; np++) {
            uint32_t addr = sb + (warp_n * 64 + np * 16 + b_row) * ROWB + b_kh * 16;
            ldsm4(fb[0][np][0], fb[0][np][1], fb[0][np][2], fb[0][np][3], addr);
        }

        #pragma unroll
        for (int ks = 0; ks < 4; ks++) {
            const int cur = ks & 1, nxt = cur ^ 1;
            if (ks < 3) {
                #pragma unroll
                for (int mt = 0; mt < 2; mt++) {
                    uint32_t addr = sa + (warp_m * 32 + mt * 16 + a_row) * ROWB
                                  + (ks + 1) * 32 + a_kh * 16;
                    ldsm4(fa[nxt][mt][0], fa[nxt][mt][1], fa[nxt][mt][2], fa[nxt][mt][3], addr);
                }
                #pragma unroll
                for (int np = 0; np < 4; np++) {
                    uint32_t addr = sb + (warp_n * 64 + np * 16 + b_row) * ROWB
                                  + (ks + 1) * 32 + b_kh * 16;
                    ldsm4(fb[nxt][np][0], fb[nxt][np][1], fb[nxt][np][2], fb[nxt][np][3], addr);
                }
            }
            #pragma unroll
            for (int mt = 0; mt < 2; mt++)
                #pragma unroll
                for (int nt = 0; nt < 8; nt++)
                    mma_bf16(acc[mt][nt][0], acc[mt][nt][1], acc[mt][nt][2], acc[mt][nt][3],
                             fa[cur][mt][0], fa[cur][mt][1], fa[cur][mt][2], fa[cur][mt][3],
                             fb[cur][nt >> 1][(nt & 1) * 2], fb[cur][nt >> 1][(nt & 1) * 2 + 1]);
        }
        // no trailing __syncthreads: next iteration's leading sync orders reuse
    }

    const int er = lane >> 2;
    const int ec = (lane & 3) * 2;
    #pragma unroll
    for (int mt = 0; mt < 2; mt++) {
        #pragma unroll
        for (int nt = 0; nt < 8; nt++) {
            int row = m0 + warp_m * 32 + mt * 16 + er;
            int col = n0 + warp_n * 64 + nt * 8 + ec;
            epi_pair<MODE>(row,     col, acc[mt][nt][0], acc[mt][nt][1],
                           b0, b1, b2, b3, b4, resid, o0, o1, o2, o3, o4);
            epi_pair<MODE>(row + 8, col, acc[mt][nt][2], acc[mt][nt][3],
                           b0, b1, b2, b3, b4, resid, o0, o1, o2, o3, o4);
        }
    }
}

// ---------------- merged weight convert: triple [hi|hi|lo] ----------------
__global__ void cvt_all(const float* __restrict__ Wupl, const float* __restrict__ Wupr,
                        const float* __restrict__ Wskip, const float* __restrict__ Wq,
                        const float* __restrict__ Wk, const float* __restrict__ Wi,
                        const float* __restrict__ Wf, const float* __restrict__ Wv,
                        const float* __restrict__ Wo, const float* __restrict__ Wdn,
                        __nv_bfloat16* __restrict__ wup, __nv_bfloat16* __restrict__ wxc,
                        __nv_bfloat16* __restrict__ wxt, __nv_bfloat16* __restrict__ wdn)
{
    int idx = blockIdx.x * 256 + threadIdx.x;
    const float* src; __nv_bfloat16* dst; int K, KE, rowOff, local;
    if      (idx < 2097152) { src = Wupl;  dst = wup; K = 1024; KE = KE_XN; rowOff = 0;    local = idx; }
    else if (idx < 2621440) { src = Wupr;  dst = wup; K = 1024; KE = KE_XN; rowOff = 2048; local = idx - 2097152; }
    else if (idx < 3670016) { src = Wskip; dst = wxc; K = 2048; KE = KE_P;  rowOff = 0;    local = idx - 2621440; }
    else if (idx < 4718592) { src = Wq;    dst = wxc; K = 2048; KE = KE_P;  rowOff = 512;  local = idx - 3670016; }
    else if (idx < 5767168) { src = Wk;    dst = wxc; K = 2048; KE = KE_P;  rowOff = 1024; local = idx - 4718592; }
    else if (idx < 5783552) { src = Wi;    dst = wxc; K = 2048; KE = KE_P;  rowOff = 1536; local = idx - 5767168; }
    else if (idx < 5799936) { src = Wf;    dst = wxc; K = 2048; KE = KE_P;  rowOff = 1544; local = idx - 5783552; }
    else if (idx < 6848512) { src = Wv;    dst = wxt; K = 2048; KE = KE_P;  rowOff = 0;    local = idx - 5799936; }
    else if (idx < 7897088) { src = Wo;    dst = wxt; K = 2048; KE = KE_P;  rowOff = 512;  local = idx - 6848512; }
    else if (idx < 8421376) { src = Wdn;   dst = wdn; K = 512;  KE = KE_UB; rowOff = 0;    local = idx - 7897088; }
    else return;
    int r = local / K, k = local - r * K;
    float x = src[local];
    __nv_bfloat16 hi, lo;
    split2(x, hi, lo);
    size_t b = (size_t)(rowOff + r) * KE + k;
    dst[b] = hi; dst[b + K] = hi; dst[b + 2 * K] = lo;
}

// ---------------- LayerNorm -> xn dual [hi|lo] ----------------
__global__ void ln_kernel(const float* __restrict__ x, const float* __restrict__ g,
                          const float* __restrict__ b, __nv_bfloat16* __restrict__ out2)
{
    int tok = blockIdx.x;
    int tid = threadIdx.x;                 // 256
    const float4* xr = (const float4*)(x + (size_t)tok * D_);
    float4 v = xr[tid];
    float s1 = v.x + v.y + v.z + v.w;
    float s2 = v.x * v.x + v.y * v.y + v.z * v.z + v.w * v.w;
    for (int o = 16; o > 0; o >>= 1) {
        s1 += __shfl_down_sync(0xffffffffu, s1, o);
        s2 += __shfl_down_sync(0xffffffffu, s2, o);
    }
    __shared__ float ps1[8], ps2[8];
    int wid = tid >> 5, lane = tid & 31;
    if (lane == 0) { ps1[wid] = s1; ps2[wid] = s2; }
    __syncthreads();
    float S1 = 0.f, S2 = 0.f;
    #pragma unroll
    for (int w = 0; w < 8; w++) { S1 += ps1[w]; S2 += ps2[w]; }
    float mu = S1 * (1.0f / D_);
    float var = S2 * (1.0f / D_) - mu * mu;
    float r = rsqrtf(var + EPS);

    float4 gv = ((const float4*)g)[tid];
    float4 bv = ((const float4*)b)[tid];
    float vals[4] = { (v.x - mu) * r * gv.x + bv.x, (v.y - mu) * r * gv.y + bv.y,
                      (v.z - mu) * r * gv.z + bv.z, (v.w - mu) * r * gv.w + bv.w };
    __nv_bfloat16 h[4], l[4];
    #pragma unroll
    for (int i = 0; i < 4; i++) split2(vals[i], h[i], l[i]);
    size_t base = (size_t)tok * 2048 + tid * 4;
    *(__nv_bfloat162*)(out2 + base)            = __nv_bfloat162(h[0], h[1]);
    *(__nv_bfloat162*)(out2 + base + 2)        = __nv_bfloat162(h[2], h[3]);
    *(__nv_bfloat162*)(out2 + base + 1024)     = __nv_bfloat162(l[0], l[1]);
    *(__nv_bfloat162*)(out2 + base + 1024 + 2) = __nv_bfloat162(l[2], l[3]);
}

// ---------------- causal feature conv + SiLU: xt2 -> xc2 ----------------
__global__ void conv_silu_kernel(const __nv_bfloat16* __restrict__ xt2,
                                 const float* __restrict__ w, const float* __restrict__ cb,
                                 __nv_bfloat16* __restrict__ xc2)
{
    __shared__ float row[P_];
    int tok = blockIdx.x;
    int tid = threadIdx.x;        // 256
    const __nv_bfloat162* hi2 = (const __nv_bfloat162*)(xt2 + (size_t)tok * 4096);
    const __nv_bfloat162* lo2 = (const __nv_bfloat162*)(xt2 + (size_t)tok * 4096 + 2048);
    #pragma unroll
    for (int i = 0; i < 4; i++) {
        int idx = tid + i * 256;          // 0..1023 pairs
        __nv_bfloat162 hp = hi2[idx], lp = lo2[idx];
        row[2 * idx]     = __bfloat162float(hp.x) + __bfloat162float(lp.x);
        row[2 * idx + 1] = __bfloat162float(hp.y) + __bfloat162float(lp.y);
    }
    __syncthreads();

    float w0 = w[0], w1 = w[1], w2 = w[2], w3 = w[3];
    float bb = cb[0];
    __nv_bfloat16 h[8], l[8];
    #pragma unroll
    for (int i = 0; i < 8; i++) {
        int p = tid * 8 + i;
        float x3 = row[p];
        float x2 = (p >= 1) ? row[p - 1] : 0.f;
        float x1 = (p >= 2) ? row[p - 2] : 0.f;
        float x0 = (p >= 3) ? row[p - 3] : 0.f;
        float v = bb + w0 * x0 + w1 * x1 + w2 * x2 + w3 * x3;
        v = v / (1.0f + __expf(-v));
        split2(v, h[i], l[i]);
    }
    size_t base = (size_t)tok * 4096 + tid * 8;
    #pragma unroll
    for (int i = 0; i < 4; i++) {
        *(__nv_bfloat162*)(xc2 + base + 2 * i)        = __nv_bfloat162(h[2 * i], h[2 * i + 1]);
        *(__nv_bfloat162*)(xc2 + base + 2048 + 2 * i) = __nv_bfloat162(l[2 * i], l[2 * i + 1]);
    }
}

// ---------------- sequential mLSTM recurrence: 64 blocks x 256 threads ----------------
__global__ void __launch_bounds__(256) recur_kernel(
    const float* __restrict__ q, const float* __restrict__ k, const float* __restrict__ v,
    const float* __restrict__ ip, const float* __restrict__ fp, float* __restrict__ hs)
{
    int bh = blockIdx.x;
    int b = bh >> 3, h = bh & 7;
    int t = threadIdx.x;
    int d = t & 63, quarter = t >> 6;     // 4 quarters of the k dimension

    __shared__ __align__(16) float q_s[64], k_s[64], v_s[64];
    __shared__ float n_s[64];
    __shared__ float num_s[256];
    __shared__ float den_s[2];

    float c[16];
    #pragma unroll
    for (int j = 0; j < 16; j++) c[j] = 0.f;
    if (t < 64) n_s[t] = 1.f;
    float m = 0.f;

    size_t gbase = (size_t)b * S_ * HID_ + (size_t)h * HD_ + d;
    size_t ifbase = (size_t)b * S_ * H_ + h;

    float qr = 0.f, kr = 0.f, vr = 0.f;
    if (t < 64) { qr = q[gbase]; kr = k[gbase]; vr = v[gbase]; }
    float ir = ip[ifbase], fr = fp[ifbase];

    for (int s = 0; s < S_; s++) {
        if (t < 64) { q_s[t] = qr; k_s[t] = kr; v_s[t] = vr; }
        float it = ir, ft = fr;
        __syncthreads();

        if (s + 1 < S_) {
            size_t off = gbase + (size_t)(s + 1) * HID_;
            if (t < 64) { qr = q[off]; kr = k[off]; vr = v[off]; }
            size_t ioff = ifbase + (size_t)(s + 1) * H_;
            ir = ip[ioff]; fr = fp[ioff];
        }

        float m_t = fmaxf(ft + m, it);
        float ie  = __expf(it - m_t);
        float fe  = __expf(ft - m_t + m);
        m = m_t;

        float ievd = ie * v_s[d];
        float np0 = 0.f, np1 = 0.f, np2 = 0.f, np3 = 0.f;
        const float4* k4 = (const float4*)(k_s + quarter * 16);
        const float4* q4 = (const float4*)(q_s + quarter * 16);
        #pragma unroll
        for (int j = 0; j < 4; j++) {
            float4 kk = k4[j], qq = q4[j];
            float c0 = fmaf(fe, c[4 * j + 0], ievd * kk.x); c[4 * j + 0] = c0; np0 = fmaf(c0, qq.x, np0);
            float c1 = fmaf(fe, c[4 * j + 1], ievd * kk.y); c[4 * j + 1] = c1; np1 = fmaf(c1, qq.y, np1);
            float c2 = fmaf(fe, c[4 * j + 2], ievd * kk.z); c[4 * j + 2] = c2; np2 = fmaf(c2, qq.z, np2);
            float c3 = fmaf(fe, c[4 * j + 3], ievd * kk.w); c[4 * j + 3] = c3; np3 = fmaf(c3, qq.w, np3);
        }
        num_s[t] = (np0 + np1) + (np2 + np3);

        float denp = 0.f;
        if (t < 64) {
            float nn = fmaf(fe, n_s[t], ie * k_s[t]);
            n_s[t] = nn;
            denp = nn * q_s[t];
        }
        #pragma unroll
        for (int o = 16; o > 0; o >>= 1) denp += __shfl_down_sync(0xffffffffu, denp, o);
        if (t < 64 && (t & 31) == 0) den_s[t >> 5] = denp;
        __syncthreads();

        if (t < 64) {
            float den = fmaxf(den_s[0] + den_s[1], 1.0f);
            hs[gbase + (size_t)s * HID_] =
                ((num_s[t] + num_s[64 + t]) + (num_s[128 + t] + num_s[192 + t])) / den;
        }
    }
}

// ---------------- mix: o*hs, per-head LN, + skip, * silu(r_t) -> ub dual ----------------
__global__ void mix_kernel(const float* __restrict__ hs, const float* __restrict__ o,
                           const float* __restrict__ skip, const float* __restrict__ rt,
                           const float* __restrict__ mhg, const float* __restrict__ mhb,
                           __nv_bfloat16* __restrict__ ub2)
{
    int tok = blockIdx.x;
    int tid = threadIdx.x;          // 512
    int head = tid >> 6;
    size_t idx = (size_t)tok * HID_ + tid;

    float val = o[idx] * hs[idx];
    float s1 = val, s2 = val * val;
    for (int off = 16; off > 0; off >>= 1) {
        s1 += __shfl_down_sync(0xffffffffu, s1, off);
        s2 += __shfl_down_sync(0xffffffffu, s2, off);
    }
    __shared__ float ps1[16], ps2[16];
    int wid = tid >> 5, lane = tid & 31;
    if (lane == 0) { ps1[wid] = s1; ps2[wid] = s2; }
    __syncthreads();
    float S1 = ps1[head * 2] + ps1[head * 2 + 1];
    float S2 = ps2[head * 2] + ps2[head * 2 + 1];
    float mu = S1 * (1.0f / HD_);
    float var = S2 * (1.0f / HD_) - mu * mu;
    float r = rsqrtf(var + EPS);

    float hn = (val - mu) * r * mhg[tid] + mhb[tid];
    float rv = rt[idx];
    float u = (hn + skip[idx]) * (rv / (1.0f + __expf(-rv)));

    __nv_bfloat16 hi, lo;
    split2(u, hi, lo);
    size_t b = (size_t)tok * 1024 + tid;
    ub2[b] = hi; ub2[b + 512] = lo;
}

// ---------------- host launcher ----------------
extern "C" void kernel_launch(void* const* d_in, const int* in_sizes, int n_in,
                              void* d_out, int out_size)
{
    const float* x      = (const float*)d_in[0];
    const float* ln_g   = (const float*)d_in[1];
    const float* ln_b   = (const float*)d_in[2];
    const float* mh_g   = (const float*)d_in[3];
    const float* mh_b   = (const float*)d_in[4];
    const float* W_up_l = (const float*)d_in[5];
    const float* b_up_l = (const float*)d_in[6];
    const float* W_up_r = (const float*)d_in[7];
    const float* b_up_r = (const float*)d_in[8];
    const float* W_down = (const float*)d_in[9];
    const float* b_down = (const float*)d_in[10];
    const float* conv_w = (const float*)d_in[11];
    const float* conv_b = (const float*)d_in[12];
    const float* W_skip = (const float*)d_in[13];
    const float* b_skip = (const float*)d_in[14];
    const float* W_i    = (const float*)d_in[15];
    const float* b_i    = (const float*)d_in[16];
    const float* W_f    = (const float*)d_in[17];
    const float* b_f    = (const float*)d_in[18];
    const float* W_o    = (const float*)d_in[19];
    const float* b_o    = (const float*)d_in[20];
    const float* W_q    = (const float*)d_in[21];
    const float* b_q    = (const float*)d_in[22];
    const float* W_k    = (const float*)d_in[23];
    const float* b_k    = (const float*)d_in[24];
    const float* W_v    = (const float*)d_in[25];
    const float* b_v    = (const float*)d_in[26];
    float* out = (float*)d_out;

    float *rt, *skip, *qb, *kb, *vb, *ob, *ib, *fb, *hsb;
    __nv_bfloat16 *xn2, *xt2, *xc2, *ub2, *wup, *wxc, *wxt, *wdn;
    cudaGetSymbolAddress((void**)&rt,   g_rt);
    cudaGetSymbolAddress((void**)&skip, g_skip);
    cudaGetSymbolAddress((void**)&qb,   g_q);
    cudaGetSymbolAddress((void**)&kb,   g_k);
    cudaGetSymbolAddress((void**)&vb,   g_v);
    cudaGetSymbolAddress((void**)&ob,   g_o);
    cudaGetSymbolAddress((void**)&ib,   g_i);
    cudaGetSymbolAddress((void**)&fb,   g_f);
    cudaGetSymbolAddress((void**)&hsb,  g_hs);
    cudaGetSymbolAddress((void**)&xn2,  g_xn2);
    cudaGetSymbolAddress((void**)&xt2,  g_xt2);
    cudaGetSymbolAddress((void**)&xc2,  g_xc2);
    cudaGetSymbolAddress((void**)&ub2,  g_ub2);
    cudaGetSymbolAddress((void**)&wup,  g_wup);
    cudaGetSymbolAddress((void**)&wxc,  g_wxc);
    cudaGetSymbolAddress((void**)&wxt,  g_wxt);
    cudaGetSymbolAddress((void**)&wdn,  g_wdn);

    cudaFuncSetAttribute((const void*)gemm_mma<0, KE_XN>, cudaFuncAttributeMaxDynamicSharedMemorySize, GSMEM);
    cudaFuncSetAttribute((const void*)gemm_mma<2, KE_P>,  cudaFuncAttributeMaxDynamicSharedMemorySize, GSMEM);
    cudaFuncSetAttribute((const void*)gemm_mma<3, KE_P>,  cudaFuncAttributeMaxDynamicSharedMemorySize, GSMEM);
    cudaFuncSetAttribute((const void*)gemm_mma<4, KE_UB>, cudaFuncAttributeMaxDynamicSharedMemorySize, GSMEM);

    // [0] merged weight conversion (wxc rows 1552.. stay zero-initialized)
    cvt_all<<<32896, 256>>>(W_up_l, W_up_r, W_skip, W_q, W_k, W_i, W_f, W_v, W_o, W_down,
                            wup, wxc, wxt, wdn);

    // [1] layernorm -> xn dual
    ln_kernel<<<TOK, 256>>>(x, ln_g, ln_b, xn2);

    // [2] merged up projection: xt2 | rt
    {
        dim3 grid(2560 / NTILE, TOK / MTILE);
        gemm_mma<0, KE_XN><<<grid, 256, GSMEM>>>(xn2, wup, b_up_l, b_up_r, nullptr, nullptr, nullptr,
                                                 nullptr, (float*)xt2, rt, nullptr, nullptr, nullptr);
    }

    // [3] causal conv + silu: xt2 -> xc2
    conv_silu_kernel<<<TOK, 256>>>(xt2, conv_w, conv_b, xc2);

    // [4] skip|q|k|i|f
    {
        dim3 grid(1664 / NTILE, TOK / MTILE);
        gemm_mma<2, KE_P><<<grid, 256, GSMEM>>>(xc2, wxc, b_skip, b_q, b_k, b_i, b_f,
                                                nullptr, skip, qb, kb, ib, fb);
    }
    // [5] v|o  (profiled by ncu)
    {
        dim3 grid(1024 / NTILE, TOK / MTILE);
        gemm_mma<3, KE_P><<<grid, 256, GSMEM>>>(xt2, wxt, b_v, b_o, nullptr, nullptr, nullptr,
                                                nullptr, vb, ob, nullptr, nullptr, nullptr);
    }

    // [6] sequential recurrence
    recur_kernel<<<B_ * H_, 256>>>(qb, kb, vb, ib, fb, hsb);

    // [7] mix -> ub dual
    mix_kernel<<<TOK, 512>>>(hsb, ob, skip, rt, mh_g, mh_b, ub2);

    // [8] down projection + bias + residual
    {
        dim3 grid(1024 / NTILE, TOK / MTILE);
        gemm_mma<4, KE_UB><<<grid, 256, GSMEM>>>(ub2, wdn, b_down, nullptr, nullptr, nullptr, nullptr,
                                                 x, out, nullptr, nullptr, nullptr, nullptr);
    }
}

// round 7
// speedup vs baseline: 2.7696x; 1.0103x over previous
#include <cuda_runtime.h>
#include <cuda_bf16.h>
#include <cstdint>
#include <cstddef>

// ---------------- problem constants ----------------
#define B_  8
#define S_  1024
#define D_  1024
#define H_  8
#define HD_ 64
#define HID_ 512
#define P_  2048
#define TOK (B_ * S_)          // 8192 tokens
#define EPS 1e-6f
#define CAP 15.0f

// W (triple) K widths; A (dual) widths are 2/3 of these
#define KE_XN 3072
#define KE_P  6144
#define KE_UB 1536

// ---------------- static device scratch ----------------
__device__ __align__(128) float g_rt  [(size_t)TOK * HID_];
__device__ __align__(128) float g_skip[(size_t)TOK * HID_];
__device__ __align__(128) float g_q   [(size_t)TOK * HID_];
__device__ __align__(128) float g_k   [(size_t)TOK * HID_];
__device__ __align__(128) float g_v   [(size_t)TOK * HID_];
__device__ __align__(128) float g_o   [(size_t)TOK * HID_];
__device__ __align__(128) float g_i   [(size_t)TOK * H_];
__device__ __align__(128) float g_f   [(size_t)TOK * H_];
__device__ __align__(128) float g_hs  [(size_t)TOK * HID_];

__device__ __align__(128) __nv_bfloat16 g_xn2 [(size_t)TOK * 2048];  // [hi|lo] of xn
__device__ __align__(128) __nv_bfloat16 g_xt2 [(size_t)TOK * 4096];  // [hi|lo] of x_t
__device__ __align__(128) __nv_bfloat16 g_xc2 [(size_t)TOK * 4096];  // [hi|lo] of x_c
__device__ __align__(128) __nv_bfloat16 g_ub2 [(size_t)TOK * 1024];  // [hi|lo] of u
__device__ __align__(128) __nv_bfloat16 g_wup [(size_t)2560 * KE_XN];   // up_l|up_r
__device__ __align__(128) __nv_bfloat16 g_wxc [(size_t)1664 * KE_P];    // skip|q|k|i|f|pad0
__device__ __align__(128) __nv_bfloat16 g_wxt [(size_t)1024 * KE_P];    // v|o
__device__ __align__(128) __nv_bfloat16 g_wdn [(size_t)1024 * KE_UB];

// ---------------- mma.sync GEMM config ----------------
#define MTILE 128
#define NTILE 128
#define BKE   64
#define ROWB  144
#define STAGE_A (MTILE * ROWB)
#define STAGE_B (NTILE * ROWB)
#define STAGE_BYTES (STAGE_A + STAGE_B)
#define GSMEM (2 * STAGE_BYTES)       // 73728 -> 2 CTAs/SM

__device__ __forceinline__ uint32_t smem_u32(const void* p) {
    uint32_t a;
    asm("{ .reg .u64 t; cvta.to.shared.u64 t, %1; cvt.u32.u64 %0, t; }" : "=r"(a) : "l"(p));
    return a;
}

__device__ __forceinline__ void ldsm4(uint32_t& r0, uint32_t& r1, uint32_t& r2, uint32_t& r3,
                                      uint32_t addr) {
    asm volatile("ldmatrix.sync.aligned.m8n8.x4.shared.b16 {%0,%1,%2,%3}, [%4];"
                 : "=r"(r0), "=r"(r1), "=r"(r2), "=r"(r3) : "r"(addr));
}

__device__ __forceinline__ void mma_bf16(float& c0, float& c1, float& c2, float& c3,
                                         uint32_t a0, uint32_t a1, uint32_t a2, uint32_t a3,
                                         uint32_t b0, uint32_t b1) {
    asm volatile(
        "mma.sync.aligned.m16n8k16.row.col.f32.bf16.bf16.f32 "
        "{%0,%1,%2,%3}, {%4,%5,%6,%7}, {%8,%9}, {%0,%1,%2,%3};"
        : "+f"(c0), "+f"(c1), "+f"(c2), "+f"(c3)
        : "r"(a0), "r"(a1), "r"(a2), "r"(a3), "r"(b0), "r"(b1));
}

__device__ __forceinline__ void split2(float v, __nv_bfloat16& hi, __nv_bfloat16& lo) {
    hi = __float2bfloat16(v);
    lo = __float2bfloat16(v - __bfloat162float(hi));
}

// MODE: 0 UP (n<2048: xt2 dual | n>=2048: rt fp32)
//       2 XC (skip|q|k*0.125|i softcap|f softcap)
//       3 XT (v | sigmoid->o)
//       4 DOWN (+bias+resid)
template<int MODE>
__device__ __forceinline__ void epi_pair(
    int gm, int col, float v0, float v1,
    const float* __restrict__ b0, const float* __restrict__ b1, const float* __restrict__ b2,
    const float* __restrict__ b3, const float* __restrict__ b4,
    const float* __restrict__ resid,
    float* __restrict__ o0, float* __restrict__ o1, float* __restrict__ o2,
    float* __restrict__ o3, float* __restrict__ o4)
{
    if (MODE == 0) {
        if (col < 2048) {
            v0 += b0[col]; v1 += b0[col + 1];
            __nv_bfloat16 h0, l0, h1, l1;
            split2(v0, h0, l0); split2(v1, h1, l1);
            __nv_bfloat16* xt2 = (__nv_bfloat16*)o0;
            size_t base = (size_t)gm * 4096 + col;
            *(__nv_bfloat162*)(xt2 + base)        = __nv_bfloat162(h0, h1);
            *(__nv_bfloat162*)(xt2 + base + 2048) = __nv_bfloat162(l0, l1);
        } else {
            int nn = col - 2048;
            float2 r = make_float2(v0 + b1[nn], v1 + b1[nn + 1]);
            *(float2*)(o1 + (size_t)gm * 512 + nn) = r;
        }
    } else if (MODE == 2) {
        if (col < 1536) {
            int seg = col >> 9, nn = col & 511;
            float* op = seg == 0 ? o0 : (seg == 1 ? o1 : o2);
            const float* bp = seg == 0 ? b0 : (seg == 1 ? b1 : b2);
            float s = (seg == 2) ? 0.125f : 1.0f;
            float2 r = make_float2((v0 + bp[nn]) * s, (v1 + bp[nn + 1]) * s);
            *(float2*)(op + (size_t)gm * 512 + nn) = r;
        } else {
            int nn = col - 1536;
            if (nn < 16) {
                #pragma unroll
                for (int e = 0; e < 2; e++) {
                    int n = nn + e;
                    float v = e == 0 ? v0 : v1;
                    if (n < 8)       o3[(size_t)gm * H_ + n]     = CAP * tanhf((v + b3[n]) * (1.0f / CAP));
                    else if (n < 16) o4[(size_t)gm * H_ + n - 8] = CAP * tanhf((v + b4[n - 8]) * (1.0f / CAP));
                }
            }
        }
    } else if (MODE == 3) {
        int seg = col >> 9, nn = col & 511;
        if (seg == 0) {
            float2 r = make_float2(v0 + b0[nn], v1 + b0[nn + 1]);
            *(float2*)(o0 + (size_t)gm * 512 + nn) = r;
        } else {
            float x0 = v0 + b1[nn], x1 = v1 + b1[nn + 1];
            float2 r = make_float2(1.0f / (1.0f + __expf(-x0)), 1.0f / (1.0f + __expf(-x1)));
            *(float2*)(o1 + (size_t)gm * 512 + nn) = r;
        }
    } else {
        float2 rr = *(const float2*)(resid + (size_t)gm * 1024 + col);
        float2 r = make_float2(v0 + b0[col] + rr.x, v1 + b0[col + 1] + rr.y);
        *(float2*)(o0 + (size_t)gm * 1024 + col) = r;
    }
}

template<int MODE, int KE>
__global__ void __launch_bounds__(256, 2) gemm_mma(
    const __nv_bfloat16* __restrict__ A, const __nv_bfloat16* __restrict__ W,
    const float* __restrict__ b0, const float* __restrict__ b1, const float* __restrict__ b2,
    const float* __restrict__ b3, const float* __restrict__ b4,
    const float* __restrict__ resid,
    float* __restrict__ o0, float* __restrict__ o1, float* __restrict__ o2,
    float* __restrict__ o3, float* __restrict__ o4)
{
    extern __shared__ __align__(128) char dsm[];
    const uint32_t sbase = smem_u32(dsm);
    const int tid = threadIdx.x;
    const int wid = tid >> 5, lane = tid & 31;
    const int warp_m = wid >> 1;
    const int warp_n = wid & 1;

    const int m0 = blockIdx.y * MTILE;
    const int n0 = blockIdx.x * NTILE;
    constexpr int NS = KE / BKE;
    constexpr int KB = KE / 3 / BKE;        // stages per K-block
    constexpr int AW = (KE / 3) * 2;        // A dual width in elements

    auto load_stage = [&](int ss, int buf) {
        const int ass = (ss >= 2 * KB) ? ss - 2 * KB : ss;   // third block re-reads hi
        const uint32_t sa = sbase + buf * STAGE_BYTES;
        #pragma unroll
        for (int j = 0; j < 4; j++) {
            int cid = tid + j * 256;
            int r = cid >> 3, cg = cid & 7;
            const char* gA = (const char*)A + ((size_t)(m0 + r) * AW + ass * BKE) * 2 + cg * 16;
            asm volatile("cp.async.cg.shared.global [%0], [%1], 16;"
                         :: "r"(sa + r * ROWB + cg * 16), "l"(gA));
            const char* gB = (const char*)W + ((size_t)(n0 + r) * KE + ss * BKE) * 2 + cg * 16;
            asm volatile("cp.async.cg.shared.global [%0], [%1], 16;"
                         :: "r"(sa + STAGE_A + r * ROWB + cg * 16), "l"(gB));
        }
    };

    float acc[2][8][4];
    #pragma unroll
    for (int i = 0; i < 2; i++)
        #pragma unroll
        for (int j = 0; j < 8; j++)
            #pragma unroll
            for (int c = 0; c < 4; c++) acc[i][j][c] = 0.f;

    load_stage(0, 0);
    asm volatile("cp.async.commit_group;");

    const int a_row = lane & 15;
    const int a_kh  = lane >> 4;
    const int b_row = (lane & 7) | ((lane >> 4) << 3);
    const int b_kh  = (lane >> 3) & 1;

    #pragma unroll 2
    for (int s = 0; s < NS; s++) {
        const int buf = s & 1;
        asm volatile("cp.async.wait_group 0;");
        __syncthreads();       // stage s visible to all; prior compute done -> safe to overwrite other buf

        if (s + 1 < NS) load_stage(s + 1, (s + 1) & 1);
        asm volatile("cp.async.commit_group;");

        const uint32_t sa = sbase + buf * STAGE_BYTES;
        const uint32_t sb = sa + STAGE_A;

        #pragma unroll
        for (int ks = 0; ks < 4; ks++) {
            uint32_t afr[2][4];
            #pragma unroll
            for (int mt = 0; mt < 2; mt++) {
                uint32_t addr = sa + (warp_m * 32 + mt * 16 + a_row) * ROWB
                              + ks * 32 + a_kh * 16;
                ldsm4(afr[mt][0], afr[mt][1], afr[mt][2], afr[mt][3], addr);
            }
            uint32_t bfr[4][4];
            #pragma unroll
            for (int np = 0; np < 4; np++) {
                uint32_t addr = sb + (warp_n * 64 + np * 16 + b_row) * ROWB
                              + ks * 32 + b_kh * 16;
                ldsm4(bfr[np][0], bfr[np][1], bfr[np][2], bfr[np][3], addr);
            }
            #pragma unroll
            for (int mt = 0; mt < 2; mt++)
                #pragma unroll
                for (int nt = 0; nt < 8; nt++)
                    mma_bf16(acc[mt][nt][0], acc[mt][nt][1], acc[mt][nt][2], acc[mt][nt][3],
                             afr[mt][0], afr[mt][1], afr[mt][2], afr[mt][3],
                             bfr[nt >> 1][(nt & 1) * 2], bfr[nt >> 1][(nt & 1) * 2 + 1]);
        }
    }

    const int er = lane >> 2;
    const int ec = (lane & 3) * 2;
    #pragma unroll
    for (int mt = 0; mt < 2; mt++) {
        #pragma unroll
        for (int nt = 0; nt < 8; nt++) {
            int row = m0 + warp_m * 32 + mt * 16 + er;
            int col = n0 + warp_n * 64 + nt * 8 + ec;
            epi_pair<MODE>(row,     col, acc[mt][nt][0], acc[mt][nt][1],
                           b0, b1, b2, b3, b4, resid, o0, o1, o2, o3, o4);
            epi_pair<MODE>(row + 8, col, acc[mt][nt][2], acc[mt][nt][3],
                           b0, b1, b2, b3, b4, resid, o0, o1, o2, o3, o4);
        }
    }
}

// ---------------- merged weight convert: triple [hi|hi|lo] ----------------
__global__ void cvt_all(const float* __restrict__ Wupl, const float* __restrict__ Wupr,
                        const float* __restrict__ Wskip, const float* __restrict__ Wq,
                        const float* __restrict__ Wk, const float* __restrict__ Wi,
                        const float* __restrict__ Wf, const float* __restrict__ Wv,
                        const float* __restrict__ Wo, const float* __restrict__ Wdn,
                        __nv_bfloat16* __restrict__ wup, __nv_bfloat16* __restrict__ wxc,
                        __nv_bfloat16* __restrict__ wxt, __nv_bfloat16* __restrict__ wdn)
{
    int idx = blockIdx.x * 256 + threadIdx.x;
    const float* src; __nv_bfloat16* dst; int K, KE, rowOff, local;
    if      (idx < 2097152) { src = Wupl;  dst = wup; K = 1024; KE = KE_XN; rowOff = 0;    local = idx; }
    else if (idx < 2621440) { src = Wupr;  dst = wup; K = 1024; KE = KE_XN; rowOff = 2048; local = idx - 2097152; }
    else if (idx < 3670016) { src = Wskip; dst = wxc; K = 2048; KE = KE_P;  rowOff = 0;    local = idx - 2621440; }
    else if (idx < 4718592) { src = Wq;    dst = wxc; K = 2048; KE = KE_P;  rowOff = 512;  local = idx - 3670016; }
    else if (idx < 5767168) { src = Wk;    dst = wxc; K = 2048; KE = KE_P;  rowOff = 1024; local = idx - 4718592; }
    else if (idx < 5783552) { src = Wi;    dst = wxc; K = 2048; KE = KE_P;  rowOff = 1536; local = idx - 5767168; }
    else if (idx < 5799936) { src = Wf;    dst = wxc; K = 2048; KE = KE_P;  rowOff = 1544; local = idx - 5783552; }
    else if (idx < 6848512) { src = Wv;    dst = wxt; K = 2048; KE = KE_P;  rowOff = 0;    local = idx - 5799936; }
    else if (idx < 7897088) { src = Wo;    dst = wxt; K = 2048; KE = KE_P;  rowOff = 512;  local = idx - 6848512; }
    else if (idx < 8421376) { src = Wdn;   dst = wdn; K = 512;  KE = KE_UB; rowOff = 0;    local = idx - 7897088; }
    else return;
    int r = local / K, k = local - r * K;
    float x = src[local];
    __nv_bfloat16 hi, lo;
    split2(x, hi, lo);
    size_t b = (size_t)(rowOff + r) * KE + k;
    dst[b] = hi; dst[b + K] = hi; dst[b + 2 * K] = lo;
}

// ---------------- LayerNorm -> xn dual [hi|lo] ----------------
__global__ void ln_kernel(const float* __restrict__ x, const float* __restrict__ g,
                          const float* __restrict__ b, __nv_bfloat16* __restrict__ out2)
{
    int tok = blockIdx.x;
    int tid = threadIdx.x;                 // 256
    const float4* xr = (const float4*)(x + (size_t)tok * D_);
    float4 v = xr[tid];
    float s1 = v.x + v.y + v.z + v.w;
    float s2 = v.x * v.x + v.y * v.y + v.z * v.z + v.w * v.w;
    for (int o = 16; o > 0; o >>= 1) {
        s1 += __shfl_down_sync(0xffffffffu, s1, o);
        s2 += __shfl_down_sync(0xffffffffu, s2, o);
    }
    __shared__ float ps1[8], ps2[8];
    int wid = tid >> 5, lane = tid & 31;
    if (lane == 0) { ps1[wid] = s1; ps2[wid] = s2; }
    __syncthreads();
    float S1 = 0.f, S2 = 0.f;
    #pragma unroll
    for (int w = 0; w < 8; w++) { S1 += ps1[w]; S2 += ps2[w]; }
    float mu = S1 * (1.0f / D_);
    float var = S2 * (1.0f / D_) - mu * mu;
    float r = rsqrtf(var + EPS);

    float4 gv = ((const float4*)g)[tid];
    float4 bv = ((const float4*)b)[tid];
    float vals[4] = { (v.x - mu) * r * gv.x + bv.x, (v.y - mu) * r * gv.y + bv.y,
                      (v.z - mu) * r * gv.z + bv.z, (v.w - mu) * r * gv.w + bv.w };
    __nv_bfloat16 h[4], l[4];
    #pragma unroll
    for (int i = 0; i < 4; i++) split2(vals[i], h[i], l[i]);
    size_t base = (size_t)tok * 2048 + tid * 4;
    *(__nv_bfloat162*)(out2 + base)            = __nv_bfloat162(h[0], h[1]);
    *(__nv_bfloat162*)(out2 + base + 2)        = __nv_bfloat162(h[2], h[3]);
    *(__nv_bfloat162*)(out2 + base + 1024)     = __nv_bfloat162(l[0], l[1]);
    *(__nv_bfloat162*)(out2 + base + 1024 + 2) = __nv_bfloat162(l[2], l[3]);
}

// ---------------- causal feature conv + SiLU: xt2 -> xc2 ----------------
__global__ void conv_silu_kernel(const __nv_bfloat16* __restrict__ xt2,
                                 const float* __restrict__ w, const float* __restrict__ cb,
                                 __nv_bfloat16* __restrict__ xc2)
{
    __shared__ float row[P_];
    int tok = blockIdx.x;
    int tid = threadIdx.x;        // 256
    const __nv_bfloat162* hi2 = (const __nv_bfloat162*)(xt2 + (size_t)tok * 4096);
    const __nv_bfloat162* lo2 = (const __nv_bfloat162*)(xt2 + (size_t)tok * 4096 + 2048);
    #pragma unroll
    for (int i = 0; i < 4; i++) {
        int idx = tid + i * 256;          // 0..1023 pairs
        __nv_bfloat162 hp = hi2[idx], lp = lo2[idx];
        row[2 * idx]     = __bfloat162float(hp.x) + __bfloat162float(lp.x);
        row[2 * idx + 1] = __bfloat162float(hp.y) + __bfloat162float(lp.y);
    }
    __syncthreads();

    float w0 = w[0], w1 = w[1], w2 = w[2], w3 = w[3];
    float bb = cb[0];
    __nv_bfloat16 h[8], l[8];
    #pragma unroll
    for (int i = 0; i < 8; i++) {
        int p = tid * 8 + i;
        float x3 = row[p];
        float x2 = (p >= 1) ? row[p - 1] : 0.f;
        float x1 = (p >= 2) ? row[p - 2] : 0.f;
        float x0 = (p >= 3) ? row[p - 3] : 0.f;
        float v = bb + w0 * x0 + w1 * x1 + w2 * x2 + w3 * x3;
        v = v / (1.0f + __expf(-v));
        split2(v, h[i], l[i]);
    }
    size_t base = (size_t)tok * 4096 + tid * 8;
    #pragma unroll
    for (int i = 0; i < 4; i++) {
        *(__nv_bfloat162*)(xc2 + base + 2 * i)        = __nv_bfloat162(h[2 * i], h[2 * i + 1]);
        *(__nv_bfloat162*)(xc2 + base + 2048 + 2 * i) = __nv_bfloat162(l[2 * i], l[2 * i + 1]);
    }
}

// ---------------- sequential mLSTM recurrence: 64 blocks x 256 threads ----------------
__global__ void __launch_bounds__(256) recur_kernel(
    const float* __restrict__ q, const float* __restrict__ k, const float* __restrict__ v,
    const float* __restrict__ ip, const float* __restrict__ fp, float* __restrict__ hs)
{
    int bh = blockIdx.x;
    int b = bh >> 3, h = bh & 7;
    int t = threadIdx.x;
    int d = t & 63, quarter = t >> 6;     // 4 quarters of the k dimension

    __shared__ __align__(16) float q_s[64], k_s[64], v_s[64];
    __shared__ float n_s[64];
    __shared__ float num_s[256];
    __shared__ float den_s[2];

    float c[16];
    #pragma unroll
    for (int j = 0; j < 16; j++) c[j] = 0.f;
    if (t < 64) n_s[t] = 1.f;
    float m = 0.f;

    size_t gbase = (size_t)b * S_ * HID_ + (size_t)h * HD_ + d;
    size_t ifbase = (size_t)b * S_ * H_ + h;

    float qr = 0.f, kr = 0.f, vr = 0.f;
    if (t < 64) { qr = q[gbase]; kr = k[gbase]; vr = v[gbase]; }
    float ir = ip[ifbase], fr = fp[ifbase];

    for (int s = 0; s < S_; s++) {
        if (t < 64) { q_s[t] = qr; k_s[t] = kr; v_s[t] = vr; }
        float it = ir, ft = fr;
        __syncthreads();

        if (s + 1 < S_) {
            size_t off = gbase + (size_t)(s + 1) * HID_;
            if (t < 64) { qr = q[off]; kr = k[off]; vr = v[off]; }
            size_t ioff = ifbase + (size_t)(s + 1) * H_;
            ir = ip[ioff]; fr = fp[ioff];
        }

        float m_t = fmaxf(ft + m, it);
        float ie  = __expf(it - m_t);
        float fe  = __expf(ft - m_t + m);
        m = m_t;

        float ievd = ie * v_s[d];
        float np0 = 0.f, np1 = 0.f, np2 = 0.f, np3 = 0.f;
        const float4* k4 = (const float4*)(k_s + quarter * 16);
        const float4* q4 = (const float4*)(q_s + quarter * 16);
        #pragma unroll
        for (int j = 0; j < 4; j++) {
            float4 kk = k4[j], qq = q4[j];
            float c0 = fmaf(fe, c[4 * j + 0], ievd * kk.x); c[4 * j + 0] = c0; np0 = fmaf(c0, qq.x, np0);
            float c1 = fmaf(fe, c[4 * j + 1], ievd * kk.y); c[4 * j + 1] = c1; np1 = fmaf(c1, qq.y, np1);
            float c2 = fmaf(fe, c[4 * j + 2], ievd * kk.z); c[4 * j + 2] = c2; np2 = fmaf(c2, qq.z, np2);
            float c3 = fmaf(fe, c[4 * j + 3], ievd * kk.w); c[4 * j + 3] = c3; np3 = fmaf(c3, qq.w, np3);
        }
        num_s[t] = (np0 + np1) + (np2 + np3);

        float denp = 0.f;
        if (t < 64) {
            float nn = fmaf(fe, n_s[t], ie * k_s[t]);
            n_s[t] = nn;
            denp = nn * q_s[t];
        }
        #pragma unroll
        for (int o = 16; o > 0; o >>= 1) denp += __shfl_down_sync(0xffffffffu, denp, o);
        if (t < 64 && (t & 31) == 0) den_s[t >> 5] = denp;
        __syncthreads();

        if (t < 64) {
            float den = fmaxf(den_s[0] + den_s[1], 1.0f);
            hs[gbase + (size_t)s * HID_] =
                ((num_s[t] + num_s[64 + t]) + (num_s[128 + t] + num_s[192 + t])) / den;
        }
    }
}

// ---------------- mix: o*hs, per-head LN, + skip, * silu(r_t) -> ub dual ----------------
__global__ void mix_kernel(const float* __restrict__ hs, const float* __restrict__ o,
                           const float* __restrict__ skip, const float* __restrict__ rt,
                           const float* __restrict__ mhg, const float* __restrict__ mhb,
                           __nv_bfloat16* __restrict__ ub2)
{
    int tok = blockIdx.x;
    int tid = threadIdx.x;          // 512
    int head = tid >> 6;
    size_t idx = (size_t)tok * HID_ + tid;

    float val = o[idx] * hs[idx];
    float s1 = val, s2 = val * val;
    for (int off = 16; off > 0; off >>= 1) {
        s1 += __shfl_down_sync(0xffffffffu, s1, off);
        s2 += __shfl_down_sync(0xffffffffu, s2, off);
    }
    __shared__ float ps1[16], ps2[16];
    int wid = tid >> 5, lane = tid & 31;
    if (lane == 0) { ps1[wid] = s1; ps2[wid] = s2; }
    __syncthreads();
    float S1 = ps1[head * 2] + ps1[head * 2 + 1];
    float S2 = ps2[head * 2] + ps2[head * 2 + 1];
    float mu = S1 * (1.0f / HD_);
    float var = S2 * (1.0f / HD_) - mu * mu;
    float r = rsqrtf(var + EPS);

    float hn = (val - mu) * r * mhg[tid] + mhb[tid];
    float rv = rt[idx];
    float u = (hn + skip[idx]) * (rv / (1.0f + __expf(-rv)));

    __nv_bfloat16 hi, lo;
    split2(u, hi, lo);
    size_t b = (size_t)tok * 1024 + tid;
    ub2[b] = hi; ub2[b + 512] = lo;
}

// ---------------- host launcher ----------------
extern "C" void kernel_launch(void* const* d_in, const int* in_sizes, int n_in,
                              void* d_out, int out_size)
{
    const float* x      = (const float*)d_in[0];
    const float* ln_g   = (const float*)d_in[1];
    const float* ln_b   = (const float*)d_in[2];
    const float* mh_g   = (const float*)d_in[3];
    const float* mh_b   = (const float*)d_in[4];
    const float* W_up_l = (const float*)d_in[5];
    const float* b_up_l = (const float*)d_in[6];
    const float* W_up_r = (const float*)d_in[7];
    const float* b_up_r = (const float*)d_in[8];
    const float* W_down = (const float*)d_in[9];
    const float* b_down = (const float*)d_in[10];
    const float* conv_w = (const float*)d_in[11];
    const float* conv_b = (const float*)d_in[12];
    const float* W_skip = (const float*)d_in[13];
    const float* b_skip = (const float*)d_in[14];
    const float* W_i    = (const float*)d_in[15];
    const float* b_i    = (const float*)d_in[16];
    const float* W_f    = (const float*)d_in[17];
    const float* b_f    = (const float*)d_in[18];
    const float* W_o    = (const float*)d_in[19];
    const float* b_o    = (const float*)d_in[20];
    const float* W_q    = (const float*)d_in[21];
    const float* b_q    = (const float*)d_in[22];
    const float* W_k    = (const float*)d_in[23];
    const float* b_k    = (const float*)d_in[24];
    const float* W_v    = (const float*)d_in[25];
    const float* b_v    = (const float*)d_in[26];
    float* out = (float*)d_out;

    float *rt, *skip, *qb, *kb, *vb, *ob, *ib, *fb, *hsb;
    __nv_bfloat16 *xn2, *xt2, *xc2, *ub2, *wup, *wxc, *wxt, *wdn;
    cudaGetSymbolAddress((void**)&rt,   g_rt);
    cudaGetSymbolAddress((void**)&skip, g_skip);
    cudaGetSymbolAddress((void**)&qb,   g_q);
    cudaGetSymbolAddress((void**)&kb,   g_k);
    cudaGetSymbolAddress((void**)&vb,   g_v);
    cudaGetSymbolAddress((void**)&ob,   g_o);
    cudaGetSymbolAddress((void**)&ib,   g_i);
    cudaGetSymbolAddress((void**)&fb,   g_f);
    cudaGetSymbolAddress((void**)&hsb,  g_hs);
    cudaGetSymbolAddress((void**)&xn2,  g_xn2);
    cudaGetSymbolAddress((void**)&xt2,  g_xt2);
    cudaGetSymbolAddress((void**)&xc2,  g_xc2);
    cudaGetSymbolAddress((void**)&ub2,  g_ub2);
    cudaGetSymbolAddress((void**)&wup,  g_wup);
    cudaGetSymbolAddress((void**)&wxc,  g_wxc);
    cudaGetSymbolAddress((void**)&wxt,  g_wxt);
    cudaGetSymbolAddress((void**)&wdn,  g_wdn);

    cudaFuncSetAttribute((const void*)gemm_mma<0, KE_XN>, cudaFuncAttributeMaxDynamicSharedMemorySize, GSMEM);
    cudaFuncSetAttribute((const void*)gemm_mma<2, KE_P>,  cudaFuncAttributeMaxDynamicSharedMemorySize, GSMEM);
    cudaFuncSetAttribute((const void*)gemm_mma<3, KE_P>,  cudaFuncAttributeMaxDynamicSharedMemorySize, GSMEM);
    cudaFuncSetAttribute((const void*)gemm_mma<4, KE_UB>, cudaFuncAttributeMaxDynamicSharedMemorySize, GSMEM);

    // [0] merged weight conversion (wxc rows 1552.. stay zero-initialized)
    cvt_all<<<32896, 256>>>(W_up_l, W_up_r, W_skip, W_q, W_k, W_i, W_f, W_v, W_o, W_down,
                            wup, wxc, wxt, wdn);

    // [1] layernorm -> xn dual
    ln_kernel<<<TOK, 256>>>(x, ln_g, ln_b, xn2);

    // [2] merged up projection: xt2 | rt
    {
        dim3 grid(2560 / NTILE, TOK / MTILE);
        gemm_mma<0, KE_XN><<<grid, 256, GSMEM>>>(xn2, wup, b_up_l, b_up_r, nullptr, nullptr, nullptr,
                                                 nullptr, (float*)xt2, rt, nullptr, nullptr, nullptr);
    }

    // [3] causal conv + silu: xt2 -> xc2
    conv_silu_kernel<<<TOK, 256>>>(xt2, conv_w, conv_b, xc2);

    // [4] skip|q|k|i|f
    {
        dim3 grid(1664 / NTILE, TOK / MTILE);
        gemm_mma<2, KE_P><<<grid, 256, GSMEM>>>(xc2, wxc, b_skip, b_q, b_k, b_i, b_f,
                                                nullptr, skip, qb, kb, ib, fb);
    }
    // [5] v|o  (profiled by ncu)
    {
        dim3 grid(1024 / NTILE, TOK / MTILE);
        gemm_mma<3, KE_P><<<grid, 256, GSMEM>>>(xt2, wxt, b_v, b_o, nullptr, nullptr, nullptr,
                                                nullptr, vb, ob, nullptr, nullptr, nullptr);
    }

    // [6] sequential recurrence
    recur_kernel<<<B_ * H_, 256>>>(qb, kb, vb, ib, fb, hsb);

    // [7] mix -> ub dual
    mix_kernel<<<TOK, 512>>>(hsb, ob, skip, rt, mh_g, mh_b, ub2);

    // [8] down projection + bias + residual
    {
        dim3 grid(1024 / NTILE, TOK / MTILE);
        gemm_mma<4, KE_UB><<<grid, 256, GSMEM>>>(ub2, wdn, b_down, nullptr, nullptr, nullptr, nullptr,
                                                 x, out, nullptr, nullptr, nullptr, nullptr);
    }
}